// round 1
// baseline (speedup 1.0000x reference)
#include <cuda_runtime.h>
#include <math.h>
#include <stdint.h>

// ---------------- problem constants ----------------
#define B_   4
#define N_   1024
#define D_   1024
#define H_   16
#define E_   12
#define KTOP 2
#define FF_  4
#define HD_  64
#define T_   (B_*N_)      // 4096 tokens
#define A_   (T_*KTOP)    // 8192 expert assignments
#define TD   ((long long)T_*D_)  // 4194304

// ---------------- static device scratch ----------------
__device__ float g_xn  [T_*D_];
__device__ float g_probs[T_*E_];
__device__ int   g_topi[T_*KTOP];
__device__ float g_topw[T_*KTOP];
__device__ int   g_cnt [E_];
__device__ int   g_off [E_+1];
__device__ int   g_ctr [E_];
__device__ int   g_tok [A_];
__device__ int   g_aidx[T_*KTOP];
__device__ float g_proj[A_*D_];
__device__ float g_q   [T_*D_];
__device__ float g_k   [T_*D_];
__device__ float g_v   [T_*D_];
__device__ float g_vT  [T_*D_];
__device__ float g_S   [(long long)B_*H_*N_*N_];  // 256 MB scores
__device__ float g_att [T_*D_];
__device__ float g_o   [T_*D_];
__device__ float g_h   [T_*D_];
__device__ float g_hn  [T_*D_];
__device__ float g_ff1 [T_*FF_*D_];

// ---------------- helpers ----------------
__device__ __forceinline__ unsigned f2tf(float f) {
    unsigned u;
    asm("cvt.rna.tf32.f32 %0, %1;" : "=r"(u) : "f"(f));
    return u;
}

__device__ __forceinline__ void mma_tf32(float c[4],
        unsigned a0, unsigned a1, unsigned a2, unsigned a3,
        unsigned b0, unsigned b1) {
    asm volatile(
        "mma.sync.aligned.m16n8k8.row.col.f32.tf32.tf32.f32 "
        "{%0,%1,%2,%3}, {%4,%5,%6,%7}, {%8,%9}, {%0,%1,%2,%3};"
        : "+f"(c[0]), "+f"(c[1]), "+f"(c[2]), "+f"(c[3])
        : "r"(a0), "r"(a1), "r"(a2), "r"(a3), "r"(b0), "r"(b1));
}

__device__ __forceinline__ float gelu_tanh(float x) {
    float x3 = x * x * x;
    return 0.5f * x * (1.0f + tanhf(0.7978845608028654f * (x + 0.044715f * x3)));
}

__device__ __forceinline__ float block_reduce_sum(float v, float* sh) {
    int tid = threadIdx.x;
    #pragma unroll
    for (int o = 16; o; o >>= 1) v += __shfl_xor_sync(0xffffffffu, v, o);
    if ((tid & 31) == 0) sh[tid >> 5] = v;
    __syncthreads();
    if (tid < 32) {
        v = (tid < (int)(blockDim.x >> 5)) ? sh[tid] : 0.0f;
        #pragma unroll
        for (int o = 16; o; o >>= 1) v += __shfl_xor_sync(0xffffffffu, v, o);
        if (tid == 0) sh[0] = v;
    }
    __syncthreads();
    float r = sh[0];
    __syncthreads();
    return r;
}

__device__ __forceinline__ float block_reduce_max(float v, float* sh) {
    int tid = threadIdx.x;
    #pragma unroll
    for (int o = 16; o; o >>= 1) v = fmaxf(v, __shfl_xor_sync(0xffffffffu, v, o));
    if ((tid & 31) == 0) sh[tid >> 5] = v;
    __syncthreads();
    if (tid < 32) {
        v = (tid < (int)(blockDim.x >> 5)) ? sh[tid] : -3.4e38f;
        #pragma unroll
        for (int o = 16; o; o >>= 1) v = fmaxf(v, __shfl_xor_sync(0xffffffffu, v, o));
        if (tid == 0) sh[0] = v;
    }
    __syncthreads();
    float r = sh[0];
    __syncthreads();
    return r;
}

// ---------------- unified tf32 mma GEMM ----------------
// C[m,n] = sum_k A[m,k] * B[n,k]   (both K-major)
// Optional gather of A rows via per-expert segments (grouped GEMM),
// optional z-batched offsets decomposed as z = z1*zdiv + z2.
template<int BM, int BN>
__global__ void __launch_bounds__(256)
gemm_tf32(const float* __restrict__ A, const float* __restrict__ Bm,
          float* __restrict__ C,
          int N, int K, int lda, int ldb, int ldc,
          int zdiv, long long az1, long long az2,
          long long bz1, long long bz2, long long cz1, long long cz2,
          const int* __restrict__ seg_off, const int* __restrict__ tok,
          int Mfull, int epi,
          const float* __restrict__ bias, const float* __restrict__ resid,
          float scale) {
    constexpr int BK  = 16;
    constexpr int PAD = 4;
    __shared__ __align__(16) unsigned As[BM][BK + PAD];
    __shared__ __align__(16) unsigned Bs[BN][BK + PAD];

    int z  = blockIdx.z;
    int z1 = z / zdiv;
    int z2 = z - z1 * zdiv;
    const float* Ab = A  + z1 * az1 + z2 * az2;
    const float* Bb = Bm + z1 * bz1 + z2 * bz2;
    float*       Cb = C  + z1 * cz1 + z2 * cz2;

    int Mseg = Mfull;
    const int* grows = nullptr;
    if (seg_off) {
        int s = seg_off[z];
        Mseg  = seg_off[z + 1] - s;
        grows = tok + s;
        Cb    = C + (long long)s * ldc;
    }
    int m0 = blockIdx.y * BM;
    if (m0 >= Mseg) return;
    int n0 = blockIdx.x * BN;

    int tid  = threadIdx.x;
    int lane = tid & 31, warp = tid >> 5;
    int wm = warp & 1, wn = warp >> 1;   // 2 x 4 warps
    int gid = lane >> 2, tig = lane & 3;

    constexpr int WM = BM / 2;     // 64
    constexpr int WN = BN / 4;     // 32 or 16
    constexpr int MF = WM / 16;    // 4
    constexpr int NF = WN / 8;     // 4 or 2

    float acc[MF][NF][4];
    #pragma unroll
    for (int i = 0; i < MF; i++)
        #pragma unroll
        for (int j = 0; j < NF; j++)
            #pragma unroll
            for (int u = 0; u < 4; u++) acc[i][j][u] = 0.0f;

    int am = tid >> 2;          // row within tile pass (0..63)
    int ak = (tid & 3) * 4;     // k start (0,4,8,12)

    for (int k0 = 0; k0 < K; k0 += BK) {
        // ---- load A tile ----
        #pragma unroll
        for (int p = 0; p < BM / 64; p++) {
            int m  = am + p * 64;
            int gm = m0 + m;
            float4 va = make_float4(0.f, 0.f, 0.f, 0.f);
            if (gm < Mseg) {
                long long row = grows ? (long long)grows[gm] : (long long)gm;
                va = *reinterpret_cast<const float4*>(Ab + row * lda + k0 + ak);
            }
            uint4 ua = make_uint4(f2tf(va.x), f2tf(va.y), f2tf(va.z), f2tf(va.w));
            *reinterpret_cast<uint4*>(&As[m][ak]) = ua;
        }
        // ---- load B tile (K-major rows) ----
        #pragma unroll
        for (int p = 0; p < BN / 64; p++) {
            int n = am + p * 64;
            float4 vb = *reinterpret_cast<const float4*>(
                Bb + (long long)(n0 + n) * ldb + k0 + ak);
            uint4 ub = make_uint4(f2tf(vb.x), f2tf(vb.y), f2tf(vb.z), f2tf(vb.w));
            *reinterpret_cast<uint4*>(&Bs[n][ak]) = ub;
        }
        __syncthreads();

        #pragma unroll
        for (int ks = 0; ks < BK; ks += 8) {
            unsigned af[MF][4];
            #pragma unroll
            for (int i = 0; i < MF; i++) {
                int r = wm * WM + i * 16 + gid;
                af[i][0] = As[r    ][ks + tig];
                af[i][1] = As[r + 8][ks + tig];
                af[i][2] = As[r    ][ks + tig + 4];
                af[i][3] = As[r + 8][ks + tig + 4];
            }
            unsigned bf[NF][2];
            #pragma unroll
            for (int j = 0; j < NF; j++) {
                int c = wn * WN + j * 8 + gid;
                bf[j][0] = Bs[c][ks + tig];
                bf[j][1] = Bs[c][ks + tig + 4];
            }
            #pragma unroll
            for (int i = 0; i < MF; i++)
                #pragma unroll
                for (int j = 0; j < NF; j++)
                    mma_tf32(acc[i][j], af[i][0], af[i][1], af[i][2], af[i][3],
                             bf[j][0], bf[j][1]);
        }
        __syncthreads();
    }

    // ---- epilogue ----
    #pragma unroll
    for (int i = 0; i < MF; i++)
        #pragma unroll
        for (int j = 0; j < NF; j++)
            #pragma unroll
            for (int u = 0; u < 4; u++) {
                int r  = wm * WM + i * 16 + gid + (u >> 1) * 8;
                int c  = wn * WN + j * 8 + tig * 2 + (u & 1);
                int gm = m0 + r;
                if (gm >= Mseg) continue;
                int gn = n0 + c;
                float v = acc[i][j][u];
                if (epi == 1)      v *= scale;
                else if (epi == 2) v = gelu_tanh(v + bias[gn]);
                else if (epi == 3) v = v + bias[gn] + resid[(long long)gm * ldc + gn];
                Cb[(long long)gm * ldc + gn] = v;
            }
}

// ---------------- small kernels ----------------
__global__ void init_kernel() {
    int t = threadIdx.x;
    if (t < E_) g_cnt[t] = 0;
}

// LayerNorm; optionally h = x + add written to hout, LN(h) to out.
__global__ void ln_kernel(const float* __restrict__ x, const float* __restrict__ add,
                          const float* __restrict__ g, const float* __restrict__ b,
                          float* __restrict__ out, float* __restrict__ hout) {
    __shared__ float sh[33];
    long long row = blockIdx.x;
    int tid = threadIdx.x;
    float v[4];
    #pragma unroll
    for (int i = 0; i < 4; i++) {
        int c = tid + 256 * i;
        v[i] = x[row * D_ + c];
        if (add)  v[i] += add[row * D_ + c];
        if (hout) hout[row * D_ + c] = v[i];
    }
    float s = block_reduce_sum(v[0] + v[1] + v[2] + v[3], sh);
    float m = s * (1.0f / D_);
    float q = 0.f;
    #pragma unroll
    for (int i = 0; i < 4; i++) { float d = v[i] - m; q += d * d; }
    q = block_reduce_sum(q, sh);
    float rstd = rsqrtf(q * (1.0f / D_) + 1e-5f);
    #pragma unroll
    for (int i = 0; i < 4; i++) {
        int c = tid + 256 * i;
        out[row * D_ + c] = (v[i] - m) * rstd * g[c] + b[c];
    }
}

// Router: one warp per token. logits = xn @ Wr.T, softmax over 12,
// top-2, normalized weights, dense probs stored, counts accumulated.
__global__ void router_kernel(const float* __restrict__ Wr) {
    int warp = (blockIdx.x * blockDim.x + threadIdx.x) >> 5;
    int lane = threadIdx.x & 31;
    if (warp >= T_) return;
    const float* xr = g_xn + (long long)warp * D_;
    float acc[E_];
    #pragma unroll
    for (int e = 0; e < E_; e++) acc[e] = 0.f;
    for (int i = lane; i < D_; i += 32) {
        float xv = xr[i];
        #pragma unroll
        for (int e = 0; e < E_; e++) acc[e] += xv * Wr[e * D_ + i];
    }
    #pragma unroll
    for (int e = 0; e < E_; e++)
        #pragma unroll
        for (int o = 16; o; o >>= 1) acc[e] += __shfl_xor_sync(0xffffffffu, acc[e], o);
    if (lane == 0) {
        float mx = acc[0];
        #pragma unroll
        for (int e = 1; e < E_; e++) mx = fmaxf(mx, acc[e]);
        float p[E_], s = 0.f;
        #pragma unroll
        for (int e = 0; e < E_; e++) { p[e] = expf(acc[e] - mx); s += p[e]; }
        float inv = 1.0f / s;
        #pragma unroll
        for (int e = 0; e < E_; e++) { p[e] *= inv; g_probs[warp * E_ + e] = p[e]; }
        int i0 = 0;
        #pragma unroll
        for (int e = 1; e < E_; e++) if (p[e] > p[i0]) i0 = e;
        int i1 = (i0 == 0) ? 1 : 0;
        #pragma unroll
        for (int e = 0; e < E_; e++) if (e != i0 && p[e] > p[i1]) i1 = e;
        float v0 = p[i0], v1 = p[i1];
        float wsum = v0 + v1 + 1e-6f;
        g_topi[warp * 2 + 0] = i0;
        g_topi[warp * 2 + 1] = i1;
        g_topw[warp * 2 + 0] = v0 / wsum;
        g_topw[warp * 2 + 1] = v1 / wsum;
        atomicAdd(&g_cnt[i0], 1);
        atomicAdd(&g_cnt[i1], 1);
    }
}

__global__ void scan_kernel() {
    if (threadIdx.x == 0) {
        int s = 0;
        for (int e = 0; e < E_; e++) { g_off[e] = s; s += g_cnt[e]; g_ctr[e] = 0; }
        g_off[E_] = s;
    }
}

__global__ void scatter_kernel() {
    int idx = blockIdx.x * blockDim.x + threadIdx.x;
    if (idx >= A_) return;
    int t = idx >> 1;
    int e = g_topi[idx];
    int pos = g_off[e] + atomicAdd(&g_ctr[e], 1);
    g_tok[pos]  = t;
    g_aidx[idx] = pos;
    (void)t;
}

// dst[t] = w0*proj[a0] + w1*proj[a1]
__global__ void combine_kernel(float* __restrict__ dst) {
    long long t = blockIdx.x;
    int tid = threadIdx.x;
    int a0 = g_aidx[t * 2 + 0], a1 = g_aidx[t * 2 + 1];
    float w0 = g_topw[t * 2 + 0], w1 = g_topw[t * 2 + 1];
    const float* p0 = g_proj + (long long)a0 * D_;
    const float* p1 = g_proj + (long long)a1 * D_;
    #pragma unroll
    for (int i = 0; i < 4; i++) {
        int c = tid + 256 * i;
        dst[t * D_ + c] = w0 * p0[c] + w1 * p1[c];
    }
}

// vT[(bh*64+hd)*1024 + n] = v[(b*1024+n)*1024 + h*64 + hd]
__global__ void transpose_v_kernel() {
    __shared__ float tile[32][33];
    int bh = blockIdx.z;
    int b = bh >> 4, h = bh & 15;
    int n0 = blockIdx.x * 32, d0 = blockIdx.y * 32;
    int tx = threadIdx.x, ty = threadIdx.y;
    #pragma unroll
    for (int i = 0; i < 32; i += 8)
        tile[ty + i][tx] = g_v[((long long)(b * N_ + n0 + ty + i)) * D_ + h * HD_ + d0 + tx];
    __syncthreads();
    #pragma unroll
    for (int i = 0; i < 32; i += 8)
        g_vT[((long long)(bh * HD_ + d0 + ty + i)) * N_ + n0 + tx] = tile[tx][ty + i];
}

__global__ void softmax_rows_kernel() {
    __shared__ float sh[33];
    long long row = blockIdx.x;
    float* p = g_S + row * (long long)N_;
    int tid = threadIdx.x;
    float v[4];
    #pragma unroll
    for (int i = 0; i < 4; i++) v[i] = p[tid + 256 * i];
    float mx = fmaxf(fmaxf(v[0], v[1]), fmaxf(v[2], v[3]));
    mx = block_reduce_max(mx, sh);
    float s = 0.f;
    #pragma unroll
    for (int i = 0; i < 4; i++) { v[i] = expf(v[i] - mx); s += v[i]; }
    s = block_reduce_sum(s, sh);
    float inv = 1.0f / s;
    #pragma unroll
    for (int i = 0; i < 4; i++) p[tid + 256 * i] = v[i] * inv;
}

// load-balance loss -> out[TD] (if present)
__global__ void lb_kernel(float* __restrict__ out, int out_size) {
    __shared__ float sh[256];
    int tid = threadIdx.x;
    float pl[E_];
    #pragma unroll
    for (int e = 0; e < E_; e++) pl[e] = 0.f;
    for (int t = tid; t < T_; t += 256)
        #pragma unroll
        for (int e = 0; e < E_; e++) pl[e] += g_probs[t * E_ + e];
    float pe[E_];
    for (int e = 0; e < E_; e++) {
        sh[tid] = pl[e];
        __syncthreads();
        for (int o = 128; o; o >>= 1) {
            if (tid < o) sh[tid] += sh[tid + o];
            __syncthreads();
        }
        pe[e] = sh[0];
        __syncthreads();
    }
    if (tid == 0) {
        float lb = 0.f;
        float denom = (float)A_ + 1e-6f;
        for (int e = 0; e < E_; e++)
            lb += ((float)g_cnt[e] / denom) * pe[e];
        lb *= (float)E_;
        if (out_size > (int)TD) out[TD] = lb;
    }
}

// ---------------- host launch ----------------
extern "C" void kernel_launch(void* const* d_in, const int* in_sizes, int n_in,
                              void* d_out, int out_size) {
    const float* x   = (const float*)d_in[0];
    const float* Wr  = (const float*)d_in[1];
    const float* Wq  = (const float*)d_in[2];
    const float* Wk  = (const float*)d_in[3];
    const float* Wv  = (const float*)d_in[4];
    const float* Wo  = (const float*)d_in[5];
    const float* W1  = (const float*)d_in[6];
    const float* b1  = (const float*)d_in[7];
    const float* W2  = (const float*)d_in[8];
    const float* b2  = (const float*)d_in[9];
    const float* g1  = (const float*)d_in[10];
    const float* be1 = (const float*)d_in[11];
    const float* g2  = (const float*)d_in[12];
    const float* be2 = (const float*)d_in[13];
    float* out = (float*)d_out;

    float *p_xn, *p_proj, *p_q, *p_k, *p_v, *p_vT, *p_S, *p_att, *p_o, *p_h, *p_hn, *p_ff1;
    int *p_off, *p_tok;
    cudaGetSymbolAddress((void**)&p_xn,  g_xn);
    cudaGetSymbolAddress((void**)&p_proj,g_proj);
    cudaGetSymbolAddress((void**)&p_q,   g_q);
    cudaGetSymbolAddress((void**)&p_k,   g_k);
    cudaGetSymbolAddress((void**)&p_v,   g_v);
    cudaGetSymbolAddress((void**)&p_vT,  g_vT);
    cudaGetSymbolAddress((void**)&p_S,   g_S);
    cudaGetSymbolAddress((void**)&p_att, g_att);
    cudaGetSymbolAddress((void**)&p_o,   g_o);
    cudaGetSymbolAddress((void**)&p_h,   g_h);
    cudaGetSymbolAddress((void**)&p_hn,  g_hn);
    cudaGetSymbolAddress((void**)&p_ff1, g_ff1);
    cudaGetSymbolAddress((void**)&p_off, g_off);
    cudaGetSymbolAddress((void**)&p_tok, g_tok);

    const long long DD = (long long)D_ * D_;

    // 1. zero router counters
    init_kernel<<<1, 32>>>();
    // 2. LN1: xn = LN(x)
    ln_kernel<<<T_, 256>>>(x, nullptr, g1, be1, p_xn, nullptr);
    // 3. router
    router_kernel<<<T_ / 8, 256>>>(Wr);
    // 4. segment offsets
    scan_kernel<<<1, 32>>>();
    // 5. scatter assignments
    scatter_kernel<<<A_ / 256, 256>>>();

    // 6-8. grouped GEMMs for Q, K, V + combine
    dim3 ggrid(D_ / 128, A_ / 128, E_);
    gemm_tf32<128, 128><<<ggrid, 256>>>(p_xn, Wq, p_proj, D_, D_, D_, D_, D_,
        1, 0, 0, DD, 0, 0, 0, p_off, p_tok, A_, 0, nullptr, nullptr, 1.f);
    combine_kernel<<<T_, 256>>>(p_q);
    gemm_tf32<128, 128><<<ggrid, 256>>>(p_xn, Wk, p_proj, D_, D_, D_, D_, D_,
        1, 0, 0, DD, 0, 0, 0, p_off, p_tok, A_, 0, nullptr, nullptr, 1.f);
    combine_kernel<<<T_, 256>>>(p_k);
    gemm_tf32<128, 128><<<ggrid, 256>>>(p_xn, Wv, p_proj, D_, D_, D_, D_, D_,
        1, 0, 0, DD, 0, 0, 0, p_off, p_tok, A_, 0, nullptr, nullptr, 1.f);
    combine_kernel<<<T_, 256>>>(p_v);

    // 9. transpose V per head -> vT[bh*64+hd][n]
    transpose_v_kernel<<<dim3(N_ / 32, HD_ / 32, B_ * H_), dim3(32, 8)>>>();

    // 10. scores S = Q @ K^T / 8   (z = b*16 + h)
    gemm_tf32<128, 128><<<dim3(N_ / 128, N_ / 128, B_ * H_), 256>>>(
        p_q, p_k, p_S, N_, HD_, D_, D_, N_,
        H_, (long long)N_ * D_, HD_,             // A offsets: b*N*D + h*64
            (long long)N_ * D_, HD_,             // B offsets: same
            (long long)H_ * N_ * N_, (long long)N_ * N_,  // C: z*N*N
        nullptr, nullptr, N_, 1, nullptr, nullptr, 0.125f);

    // 11. softmax rows
    softmax_rows_kernel<<<(long long)B_ * H_ * N_, 256>>>();

    // 12. att = P @ V (vT K-major)  C -> att[b*N+m][h*64+hd]
    gemm_tf32<128, 64><<<dim3(HD_ / 64, N_ / 128, B_ * H_), 256>>>(
        p_S, p_vT, p_att, HD_, N_, N_, N_, D_,
        H_, (long long)H_ * N_ * N_, (long long)N_ * N_,  // A: z*N*N
            (long long)H_ * HD_ * N_, (long long)HD_ * N_, // B: z*64*N
            (long long)N_ * D_, HD_,                       // C: b*N*D + h*64
        nullptr, nullptr, N_, 0, nullptr, nullptr, 1.f);

    // 13. grouped O projection + combine
    gemm_tf32<128, 128><<<ggrid, 256>>>(p_att, Wo, p_proj, D_, D_, D_, D_, D_,
        1, 0, 0, DD, 0, 0, 0, p_off, p_tok, A_, 0, nullptr, nullptr, 1.f);
    combine_kernel<<<T_, 256>>>(p_o);

    // 14. h = x + o ; hn = LN2(h)
    ln_kernel<<<T_, 256>>>(x, p_o, g2, be2, p_hn, p_h);

    // 15. FFN1: ff1 = gelu(hn @ W1.T + b1)
    gemm_tf32<128, 128><<<dim3(FF_ * D_ / 128, T_ / 128, 1), 256>>>(
        p_hn, W1, p_ff1, FF_ * D_, D_, D_, D_, FF_ * D_,
        1, 0, 0, 0, 0, 0, 0, nullptr, nullptr, T_, 2, b1, nullptr, 1.f);

    // 16. FFN2: y = h + ff1 @ W2.T + b2  -> d_out
    gemm_tf32<128, 128><<<dim3(D_ / 128, T_ / 128, 1), 256>>>(
        p_ff1, W2, out, D_, FF_ * D_, FF_ * D_, FF_ * D_, D_,
        1, 0, 0, 0, 0, 0, 0, nullptr, nullptr, T_, 3, b2, p_h, 1.f);

    // 17. load-balance loss
    lb_kernel<<<1, 256>>>(out, out_size);
}

// round 2
// speedup vs baseline: 1.0147x; 1.0147x over previous
#include <cuda_runtime.h>
#include <math.h>
#include <stdint.h>

// ---------------- problem constants ----------------
#define B_   4
#define N_   1024
#define D_   1024
#define H_   16
#define E_   12
#define KTOP 2
#define FF_  4
#define HD_  64
#define T_   (B_*N_)      // 4096 tokens
#define A_   (T_*KTOP)    // 8192 expert assignments
#define TD   ((long long)T_*D_)  // 4194304

// ---------------- static device scratch ----------------
__device__ float g_xn  [T_*D_];
__device__ float g_probs[T_*E_];
__device__ int   g_topi[T_*KTOP];
__device__ float g_topw[T_*KTOP];
__device__ int   g_cnt [E_];
__device__ int   g_off [E_+1];
__device__ int   g_ctr [E_];
__device__ int   g_tok [A_];
__device__ int   g_aidx[T_*KTOP];
__device__ float g_proj[A_*D_];
__device__ float g_q   [T_*D_];
__device__ float g_k   [T_*D_];
__device__ float g_v   [T_*D_];
__device__ float g_att [T_*D_];
__device__ float g_o   [T_*D_];
__device__ float g_h   [T_*D_];
__device__ float g_hn  [T_*D_];
__device__ float g_ff1 [T_*FF_*D_];

// ---------------- helpers ----------------
__device__ __forceinline__ void cp_async16(void* s, const void* g, int sz) {
    unsigned sa = (unsigned)__cvta_generic_to_shared(s);
    asm volatile("cp.async.cg.shared.global [%0], [%1], 16, %2;\n"
                 :: "r"(sa), "l"(g), "r"(sz));
}
__device__ __forceinline__ void cp_commit() {
    asm volatile("cp.async.commit_group;\n");
}
template<int NN>
__device__ __forceinline__ void cp_wait() {
    asm volatile("cp.async.wait_group %0;\n" :: "n"(NN));
}

__device__ __forceinline__ void mma_tf32(float c[4],
        float a0, float a1, float a2, float a3, float b0, float b1) {
    asm volatile(
        "mma.sync.aligned.m16n8k8.row.col.f32.tf32.tf32.f32 "
        "{%0,%1,%2,%3}, {%4,%5,%6,%7}, {%8,%9}, {%0,%1,%2,%3};"
        : "+f"(c[0]), "+f"(c[1]), "+f"(c[2]), "+f"(c[3])
        : "r"(__float_as_uint(a0)), "r"(__float_as_uint(a1)),
          "r"(__float_as_uint(a2)), "r"(__float_as_uint(a3)),
          "r"(__float_as_uint(b0)), "r"(__float_as_uint(b1)));
}

__device__ __forceinline__ float fast_exp2(float x) {
    float y;
    asm("ex2.approx.f32 %0, %1;" : "=f"(y) : "f"(x));
    return y;
}

__device__ __forceinline__ float gelu_tanh(float x) {
    float x3 = x * x * x;
    return 0.5f * x * (1.0f + tanhf(0.7978845608028654f * (x + 0.044715f * x3)));
}

__device__ __forceinline__ float block_reduce_sum(float v, float* sh) {
    int tid = threadIdx.x;
    #pragma unroll
    for (int o = 16; o; o >>= 1) v += __shfl_xor_sync(0xffffffffu, v, o);
    if ((tid & 31) == 0) sh[tid >> 5] = v;
    __syncthreads();
    if (tid < 32) {
        v = (tid < (int)(blockDim.x >> 5)) ? sh[tid] : 0.0f;
        #pragma unroll
        for (int o = 16; o; o >>= 1) v += __shfl_xor_sync(0xffffffffu, v, o);
        if (tid == 0) sh[0] = v;
    }
    __syncthreads();
    float r = sh[0];
    __syncthreads();
    return r;
}

// ---------------- tf32 mma GEMM v2: BK=32, cp.async double-buffered ----------------
// C[m,n] = sum_k A[m,k] * B[n,k] (both K-major). Optional row gather (grouped),
// optional z-batching (z = z1*zdiv + z2).
template<int BM, int BN>
__global__ void __launch_bounds__(256)
gemm_tf32(const float* __restrict__ A, const float* __restrict__ Bm,
          float* __restrict__ C,
          int N, int K, int lda, int ldb, int ldc,
          int zdiv, long long az1, long long az2,
          long long bz1, long long bz2, long long cz1, long long cz2,
          const int* __restrict__ seg_off, const int* __restrict__ tok,
          int Mfull, int epi,
          const float* __restrict__ bias, const float* __restrict__ resid,
          float scale) {
    constexpr int BK  = 32;
    constexpr int LDS_ = BK + 4;   // 36 floats: bank = 4*gid+tig -> conflict-free
    extern __shared__ float smem[];
    float* As = smem;                    // [2][BM*LDS_]
    float* Bs = smem + 2 * BM * LDS_;    // [2][BN*LDS_]

    int z  = blockIdx.z;
    int z1 = z / zdiv;
    int z2 = z - z1 * zdiv;
    const float* Ab = A  + z1 * az1 + z2 * az2;
    const float* Bb = Bm + z1 * bz1 + z2 * bz2;
    float*       Cb = C  + z1 * cz1 + z2 * cz2;

    int Mseg = Mfull;
    const int* grows = nullptr;
    if (seg_off) {
        int s = seg_off[z];
        Mseg  = seg_off[z + 1] - s;
        grows = tok + s;
        Cb    = C + (long long)s * ldc;
    }
    int m0 = blockIdx.y * BM;
    if (m0 >= Mseg) return;
    int n0 = blockIdx.x * BN;

    int tid  = threadIdx.x;
    int lane = tid & 31, warp = tid >> 5;
    int wm = warp & 1, wn = warp >> 1;   // 2 x 4 warps
    int gid = lane >> 2, tig = lane & 3;

    constexpr int WM = BM / 2;     // 64
    constexpr int WN = BN / 4;     // 32
    constexpr int MF = WM / 16;    // 4
    constexpr int NF = WN / 8;     // 4

    float acc[MF][NF][4];
    #pragma unroll
    for (int i = 0; i < MF; i++)
        #pragma unroll
        for (int j = 0; j < NF; j++)
            #pragma unroll
            for (int u = 0; u < 4; u++) acc[i][j][u] = 0.0f;

    // loader: chunk = tid + 256*p ; row = chunk>>3 ; k = (chunk&7)*4
    auto issue = [&](int st, int k0) {
        float* Ad = As + st * BM * LDS_;
        #pragma unroll
        for (int p = 0; p < BM / 32; p++) {
            int chunk = tid + 256 * p;
            int m  = chunk >> 3;
            int kc = (chunk & 7) * 4;
            int gm = m0 + m;
            const float* src = Ab;
            int sz = 0;
            if (gm < Mseg) {
                long long row = grows ? (long long)grows[gm] : (long long)gm;
                src = Ab + row * (long long)lda + k0 + kc;
                sz  = 16;
            }
            cp_async16(&Ad[m * LDS_ + kc], src, sz);
        }
        float* Bd = Bs + st * BN * LDS_;
        #pragma unroll
        for (int p = 0; p < BN / 32; p++) {
            int chunk = tid + 256 * p;
            int n  = chunk >> 3;
            int kc = (chunk & 7) * 4;
            cp_async16(&Bd[n * LDS_ + kc],
                       Bb + (long long)(n0 + n) * ldb + k0 + kc, 16);
        }
        cp_commit();
    };

    int nk = K / BK;
    issue(0, 0);
    int st = 0;
    for (int it = 0; it < nk; it++) {
        if (it + 1 < nk) { issue(st ^ 1, (it + 1) * BK); cp_wait<1>(); }
        else             { cp_wait<0>(); }
        __syncthreads();

        const float* Ad = As + st * BM * LDS_;
        const float* Bd = Bs + st * BN * LDS_;
        #pragma unroll
        for (int ks = 0; ks < BK; ks += 8) {
            float af[MF][4];
            #pragma unroll
            for (int i = 0; i < MF; i++) {
                int r = wm * WM + i * 16 + gid;
                af[i][0] = Ad[r * LDS_ + ks + tig];
                af[i][1] = Ad[(r + 8) * LDS_ + ks + tig];
                af[i][2] = Ad[r * LDS_ + ks + tig + 4];
                af[i][3] = Ad[(r + 8) * LDS_ + ks + tig + 4];
            }
            float bf[NF][2];
            #pragma unroll
            for (int j = 0; j < NF; j++) {
                int c = wn * WN + j * 8 + gid;
                bf[j][0] = Bd[c * LDS_ + ks + tig];
                bf[j][1] = Bd[c * LDS_ + ks + tig + 4];
            }
            #pragma unroll
            for (int i = 0; i < MF; i++)
                #pragma unroll
                for (int j = 0; j < NF; j++)
                    mma_tf32(acc[i][j], af[i][0], af[i][1], af[i][2], af[i][3],
                             bf[j][0], bf[j][1]);
        }
        __syncthreads();
        st ^= 1;
    }

    // ---- epilogue (float2 stores) ----
    #pragma unroll
    for (int i = 0; i < MF; i++)
        #pragma unroll
        for (int j = 0; j < NF; j++)
            #pragma unroll
            for (int h2 = 0; h2 < 2; h2++) {
                int r  = wm * WM + i * 16 + gid + h2 * 8;
                int gm = m0 + r;
                if (gm >= Mseg) continue;
                int c  = wn * WN + j * 8 + tig * 2;
                int gn = n0 + c;
                float v0 = acc[i][j][h2 * 2 + 0];
                float v1 = acc[i][j][h2 * 2 + 1];
                if (epi == 1) { v0 *= scale; v1 *= scale; }
                else if (epi == 2) {
                    v0 = gelu_tanh(v0 + bias[gn]);
                    v1 = gelu_tanh(v1 + bias[gn + 1]);
                } else if (epi == 3) {
                    float2 rr = *reinterpret_cast<const float2*>(
                        resid + (long long)gm * ldc + gn);
                    v0 = v0 + bias[gn] + rr.x;
                    v1 = v1 + bias[gn + 1] + rr.y;
                }
                *reinterpret_cast<float2*>(Cb + (long long)gm * ldc + gn) =
                    make_float2(v0, v1);
            }
}

// ---------------- flash attention ----------------
// grid (N/128, B*H), 256 thr. Warp w owns q rows [w*16, w*16+16).
// Online softmax, P staged per-warp in smem for the PV mma.
#define FA_KS_STRIDE 68
#define FA_VS_STRIDE 72
#define FA_PS_STRIDE 132
#define FA_SMEM_FLOATS (128*FA_KS_STRIDE + 128*FA_VS_STRIDE + 8*16*FA_PS_STRIDE)

__global__ void __launch_bounds__(256)
flash_attn_kernel() {
    extern __shared__ float sm[];
    float* Ks = sm;                                   // [128][68]
    float* Vs = sm + 128 * FA_KS_STRIDE;              // [128][72]
    float* Ps = Vs + 128 * FA_VS_STRIDE;              // [8][16][132]

    int bh = blockIdx.y;
    int b = bh >> 4, h = bh & 15;
    int q0 = blockIdx.x * 128;
    int tid = threadIdx.x, lane = tid & 31, w = tid >> 5;
    int gid = lane >> 2, tig = lane & 3;

    const float* Qg = g_q + ((long long)(b * N_ + q0 + w * 16)) * D_ + h * HD_;
    float qf[8][4];
    #pragma unroll
    for (int kf = 0; kf < 8; kf++) {
        const float* qp = Qg + kf * 8;
        qf[kf][0] = qp[(long long)gid * D_ + tig];
        qf[kf][1] = qp[(long long)(gid + 8) * D_ + tig];
        qf[kf][2] = qp[(long long)gid * D_ + tig + 4];
        qf[kf][3] = qp[(long long)(gid + 8) * D_ + tig + 4];
    }

    float of[8][4];
    #pragma unroll
    for (int j = 0; j < 8; j++)
        #pragma unroll
        for (int u = 0; u < 4; u++) of[j][u] = 0.0f;

    float M0 = -1e30f, M1 = -1e30f, L0 = 0.f, L1 = 0.f;
    const float CE = 0.125f * 1.4426950408889634f;  // scale * log2(e)
    float* Pw = Ps + w * 16 * FA_PS_STRIDE;

    for (int kv0 = 0; kv0 < N_; kv0 += 128) {
        const float* Kg = g_k + ((long long)(b * N_ + kv0)) * D_ + h * HD_;
        const float* Vg = g_v + ((long long)(b * N_ + kv0)) * D_ + h * HD_;
        #pragma unroll
        for (int p = 0; p < 8; p++) {
            int chunk = tid + 256 * p;
            int r = chunk >> 4, c = (chunk & 15) * 4;
            cp_async16(&Ks[r * FA_KS_STRIDE + c], Kg + (long long)r * D_ + c, 16);
            cp_async16(&Vs[r * FA_VS_STRIDE + c], Vg + (long long)r * D_ + c, 16);
        }
        cp_commit();
        cp_wait<0>();
        __syncthreads();

        // S = Q @ K^T (raw, scale folded into exp)
        float sf[16][4];
        #pragma unroll
        for (int j = 0; j < 16; j++)
            #pragma unroll
            for (int u = 0; u < 4; u++) sf[j][u] = 0.0f;
        #pragma unroll
        for (int kf = 0; kf < 8; kf++) {
            int ko = kf * 8;
            #pragma unroll
            for (int j = 0; j < 16; j++) {
                int n = j * 8 + gid;
                float b0 = Ks[n * FA_KS_STRIDE + ko + tig];
                float b1 = Ks[n * FA_KS_STRIDE + ko + tig + 4];
                mma_tf32(sf[j], qf[kf][0], qf[kf][1], qf[kf][2], qf[kf][3], b0, b1);
            }
        }

        // row maxima (rows gid -> 0, gid+8 -> 1); reduce over tig lanes
        float mx0 = -1e30f, mx1 = -1e30f;
        #pragma unroll
        for (int j = 0; j < 16; j++) {
            mx0 = fmaxf(mx0, fmaxf(sf[j][0], sf[j][1]));
            mx1 = fmaxf(mx1, fmaxf(sf[j][2], sf[j][3]));
        }
        mx0 = fmaxf(mx0, __shfl_xor_sync(0xffffffffu, mx0, 1));
        mx0 = fmaxf(mx0, __shfl_xor_sync(0xffffffffu, mx0, 2));
        mx1 = fmaxf(mx1, __shfl_xor_sync(0xffffffffu, mx1, 1));
        mx1 = fmaxf(mx1, __shfl_xor_sync(0xffffffffu, mx1, 2));
        float nM0 = fmaxf(M0, mx0), nM1 = fmaxf(M1, mx1);
        float corr0 = fast_exp2(CE * (M0 - nM0));
        float corr1 = fast_exp2(CE * (M1 - nM1));

        float s0 = 0.f, s1 = 0.f;
        #pragma unroll
        for (int j = 0; j < 16; j++) {
            float p0 = fast_exp2(CE * (sf[j][0] - nM0));
            float p1 = fast_exp2(CE * (sf[j][1] - nM0));
            float p2 = fast_exp2(CE * (sf[j][2] - nM1));
            float p3 = fast_exp2(CE * (sf[j][3] - nM1));
            s0 += p0 + p1; s1 += p2 + p3;
            *reinterpret_cast<float2*>(&Pw[gid * FA_PS_STRIDE + j * 8 + tig * 2]) =
                make_float2(p0, p1);
            *reinterpret_cast<float2*>(&Pw[(gid + 8) * FA_PS_STRIDE + j * 8 + tig * 2]) =
                make_float2(p2, p3);
        }
        s0 += __shfl_xor_sync(0xffffffffu, s0, 1);
        s0 += __shfl_xor_sync(0xffffffffu, s0, 2);
        s1 += __shfl_xor_sync(0xffffffffu, s1, 1);
        s1 += __shfl_xor_sync(0xffffffffu, s1, 2);
        L0 = L0 * corr0 + s0;
        L1 = L1 * corr1 + s1;
        M0 = nM0; M1 = nM1;

        #pragma unroll
        for (int j = 0; j < 8; j++) {
            of[j][0] *= corr0; of[j][1] *= corr0;
            of[j][2] *= corr1; of[j][3] *= corr1;
        }
        __syncwarp();

        // O += P @ V
        #pragma unroll
        for (int k2 = 0; k2 < 16; k2++) {
            int ko = k2 * 8;
            float a0 = Pw[gid * FA_PS_STRIDE + ko + tig];
            float a1 = Pw[(gid + 8) * FA_PS_STRIDE + ko + tig];
            float a2 = Pw[gid * FA_PS_STRIDE + ko + tig + 4];
            float a3 = Pw[(gid + 8) * FA_PS_STRIDE + ko + tig + 4];
            #pragma unroll
            for (int j = 0; j < 8; j++) {
                float b0 = Vs[(ko + tig) * FA_VS_STRIDE + j * 8 + gid];
                float b1 = Vs[(ko + tig + 4) * FA_VS_STRIDE + j * 8 + gid];
                mma_tf32(of[j], a0, a1, a2, a3, b0, b1);
            }
        }
        __syncthreads();
    }

    float i0 = 1.0f / L0, i1 = 1.0f / L1;
    float* Og = g_att + ((long long)(b * N_ + q0 + w * 16)) * D_ + h * HD_;
    #pragma unroll
    for (int j = 0; j < 8; j++) {
        *reinterpret_cast<float2*>(&Og[(long long)gid * D_ + j * 8 + tig * 2]) =
            make_float2(of[j][0] * i0, of[j][1] * i0);
        *reinterpret_cast<float2*>(&Og[(long long)(gid + 8) * D_ + j * 8 + tig * 2]) =
            make_float2(of[j][2] * i1, of[j][3] * i1);
    }
}

// ---------------- small kernels ----------------
__global__ void init_kernel() {
    int t = threadIdx.x;
    if (t < E_) g_cnt[t] = 0;
}

__global__ void ln_kernel(const float* __restrict__ x, const float* __restrict__ add,
                          const float* __restrict__ g, const float* __restrict__ b,
                          float* __restrict__ out, float* __restrict__ hout) {
    __shared__ float sh[33];
    long long row = blockIdx.x;
    int tid = threadIdx.x;
    float v[4];
    #pragma unroll
    for (int i = 0; i < 4; i++) {
        int c = tid + 256 * i;
        v[i] = x[row * D_ + c];
        if (add)  v[i] += add[row * D_ + c];
        if (hout) hout[row * D_ + c] = v[i];
    }
    float s = block_reduce_sum(v[0] + v[1] + v[2] + v[3], sh);
    float m = s * (1.0f / D_);
    float q = 0.f;
    #pragma unroll
    for (int i = 0; i < 4; i++) { float d = v[i] - m; q += d * d; }
    q = block_reduce_sum(q, sh);
    float rstd = rsqrtf(q * (1.0f / D_) + 1e-5f);
    #pragma unroll
    for (int i = 0; i < 4; i++) {
        int c = tid + 256 * i;
        out[row * D_ + c] = (v[i] - m) * rstd * g[c] + b[c];
    }
}

__global__ void router_kernel(const float* __restrict__ Wr) {
    int warp = (blockIdx.x * blockDim.x + threadIdx.x) >> 5;
    int lane = threadIdx.x & 31;
    if (warp >= T_) return;
    const float* xr = g_xn + (long long)warp * D_;
    float acc[E_];
    #pragma unroll
    for (int e = 0; e < E_; e++) acc[e] = 0.f;
    for (int i = lane; i < D_; i += 32) {
        float xv = xr[i];
        #pragma unroll
        for (int e = 0; e < E_; e++) acc[e] += xv * Wr[e * D_ + i];
    }
    #pragma unroll
    for (int e = 0; e < E_; e++)
        #pragma unroll
        for (int o = 16; o; o >>= 1) acc[e] += __shfl_xor_sync(0xffffffffu, acc[e], o);
    if (lane == 0) {
        float mx = acc[0];
        #pragma unroll
        for (int e = 1; e < E_; e++) mx = fmaxf(mx, acc[e]);
        float p[E_], s = 0.f;
        #pragma unroll
        for (int e = 0; e < E_; e++) { p[e] = expf(acc[e] - mx); s += p[e]; }
        float inv = 1.0f / s;
        #pragma unroll
        for (int e = 0; e < E_; e++) { p[e] *= inv; g_probs[warp * E_ + e] = p[e]; }
        int i0 = 0;
        #pragma unroll
        for (int e = 1; e < E_; e++) if (p[e] > p[i0]) i0 = e;
        int i1 = (i0 == 0) ? 1 : 0;
        #pragma unroll
        for (int e = 0; e < E_; e++) if (e != i0 && p[e] > p[i1]) i1 = e;
        float v0 = p[i0], v1 = p[i1];
        float wsum = v0 + v1 + 1e-6f;
        g_topi[warp * 2 + 0] = i0;
        g_topi[warp * 2 + 1] = i1;
        g_topw[warp * 2 + 0] = v0 / wsum;
        g_topw[warp * 2 + 1] = v1 / wsum;
        atomicAdd(&g_cnt[i0], 1);
        atomicAdd(&g_cnt[i1], 1);
    }
}

__global__ void scan_kernel() {
    if (threadIdx.x == 0) {
        int s = 0;
        for (int e = 0; e < E_; e++) { g_off[e] = s; s += g_cnt[e]; g_ctr[e] = 0; }
        g_off[E_] = s;
    }
}

__global__ void scatter_kernel() {
    int idx = blockIdx.x * blockDim.x + threadIdx.x;
    if (idx >= A_) return;
    int t = idx >> 1;
    int e = g_topi[idx];
    int pos = g_off[e] + atomicAdd(&g_ctr[e], 1);
    g_tok[pos]  = t;
    g_aidx[idx] = pos;
    (void)t;
}

__global__ void combine_kernel(float* __restrict__ dst) {
    long long t = blockIdx.x;
    int tid = threadIdx.x;
    int a0 = g_aidx[t * 2 + 0], a1 = g_aidx[t * 2 + 1];
    float w0 = g_topw[t * 2 + 0], w1 = g_topw[t * 2 + 1];
    const float* p0 = g_proj + (long long)a0 * D_;
    const float* p1 = g_proj + (long long)a1 * D_;
    #pragma unroll
    for (int i = 0; i < 4; i++) {
        int c = tid + 256 * i;
        dst[t * D_ + c] = w0 * p0[c] + w1 * p1[c];
    }
}

__global__ void lb_kernel(float* __restrict__ out, int out_size) {
    __shared__ float sh[256];
    int tid = threadIdx.x;
    float pl[E_];
    #pragma unroll
    for (int e = 0; e < E_; e++) pl[e] = 0.f;
    for (int t = tid; t < T_; t += 256)
        #pragma unroll
        for (int e = 0; e < E_; e++) pl[e] += g_probs[t * E_ + e];
    float pe[E_];
    for (int e = 0; e < E_; e++) {
        sh[tid] = pl[e];
        __syncthreads();
        for (int o = 128; o; o >>= 1) {
            if (tid < o) sh[tid] += sh[tid + o];
            __syncthreads();
        }
        pe[e] = sh[0];
        __syncthreads();
    }
    if (tid == 0) {
        float lb = 0.f;
        float denom = (float)A_ + 1e-6f;
        for (int e = 0; e < E_; e++)
            lb += ((float)g_cnt[e] / denom) * pe[e];
        lb *= (float)E_;
        if (out_size > (int)TD) out[TD] = lb;
    }
}

// ---------------- host launch ----------------
extern "C" void kernel_launch(void* const* d_in, const int* in_sizes, int n_in,
                              void* d_out, int out_size) {
    const float* x   = (const float*)d_in[0];
    const float* Wr  = (const float*)d_in[1];
    const float* Wq  = (const float*)d_in[2];
    const float* Wk  = (const float*)d_in[3];
    const float* Wv  = (const float*)d_in[4];
    const float* Wo  = (const float*)d_in[5];
    const float* W1  = (const float*)d_in[6];
    const float* b1  = (const float*)d_in[7];
    const float* W2  = (const float*)d_in[8];
    const float* b2  = (const float*)d_in[9];
    const float* g1  = (const float*)d_in[10];
    const float* be1 = (const float*)d_in[11];
    const float* g2  = (const float*)d_in[12];
    const float* be2 = (const float*)d_in[13];
    float* out = (float*)d_out;

    float *p_xn, *p_proj, *p_q, *p_k, *p_v, *p_att, *p_o, *p_h, *p_hn, *p_ff1;
    int *p_off, *p_tok;
    cudaGetSymbolAddress((void**)&p_xn,  g_xn);
    cudaGetSymbolAddress((void**)&p_proj,g_proj);
    cudaGetSymbolAddress((void**)&p_q,   g_q);
    cudaGetSymbolAddress((void**)&p_k,   g_k);
    cudaGetSymbolAddress((void**)&p_v,   g_v);
    cudaGetSymbolAddress((void**)&p_att, g_att);
    cudaGetSymbolAddress((void**)&p_o,   g_o);
    cudaGetSymbolAddress((void**)&p_h,   g_h);
    cudaGetSymbolAddress((void**)&p_hn,  g_hn);
    cudaGetSymbolAddress((void**)&p_ff1, g_ff1);
    cudaGetSymbolAddress((void**)&p_off, g_off);
    cudaGetSymbolAddress((void**)&p_tok, g_tok);

    const long long DD = (long long)D_ * D_;
    const int GEMM_SMEM = 2 * (128 + 128) * 36 * 4;       // 73728 B
    const int FA_SMEM   = FA_SMEM_FLOATS * 4;             // 139264 B
    cudaFuncSetAttribute(gemm_tf32<128, 128>,
                         cudaFuncAttributeMaxDynamicSharedMemorySize, GEMM_SMEM);
    cudaFuncSetAttribute(flash_attn_kernel,
                         cudaFuncAttributeMaxDynamicSharedMemorySize, FA_SMEM);

    init_kernel<<<1, 32>>>();
    ln_kernel<<<T_, 256>>>(x, nullptr, g1, be1, p_xn, nullptr);
    router_kernel<<<T_ / 8, 256>>>(Wr);
    scan_kernel<<<1, 32>>>();
    scatter_kernel<<<A_ / 256, 256>>>();

    // grouped GEMMs for Q, K, V + combine
    dim3 ggrid(D_ / 128, A_ / 128, E_);
    gemm_tf32<128, 128><<<ggrid, 256, GEMM_SMEM>>>(p_xn, Wq, p_proj, D_, D_, D_, D_, D_,
        1, 0, 0, DD, 0, 0, 0, p_off, p_tok, A_, 0, nullptr, nullptr, 1.f);
    combine_kernel<<<T_, 256>>>(p_q);
    gemm_tf32<128, 128><<<ggrid, 256, GEMM_SMEM>>>(p_xn, Wk, p_proj, D_, D_, D_, D_, D_,
        1, 0, 0, DD, 0, 0, 0, p_off, p_tok, A_, 0, nullptr, nullptr, 1.f);
    combine_kernel<<<T_, 256>>>(p_k);
    gemm_tf32<128, 128><<<ggrid, 256, GEMM_SMEM>>>(p_xn, Wv, p_proj, D_, D_, D_, D_, D_,
        1, 0, 0, DD, 0, 0, 0, p_off, p_tok, A_, 0, nullptr, nullptr, 1.f);
    combine_kernel<<<T_, 256>>>(p_v);

    // fused attention (QK^T -> online softmax -> PV)
    flash_attn_kernel<<<dim3(N_ / 128, B_ * H_), 256, FA_SMEM>>>();

    // grouped O projection + combine
    gemm_tf32<128, 128><<<ggrid, 256, GEMM_SMEM>>>(p_att, Wo, p_proj, D_, D_, D_, D_, D_,
        1, 0, 0, DD, 0, 0, 0, p_off, p_tok, A_, 0, nullptr, nullptr, 1.f);
    combine_kernel<<<T_, 256>>>(p_o);

    // h = x + o ; hn = LN2(h)
    ln_kernel<<<T_, 256>>>(x, p_o, g2, be2, p_hn, p_h);

    // FFN1: ff1 = gelu(hn @ W1.T + b1)
    gemm_tf32<128, 128><<<dim3(FF_ * D_ / 128, T_ / 128, 1), 256, GEMM_SMEM>>>(
        p_hn, W1, p_ff1, FF_ * D_, D_, D_, D_, FF_ * D_,
        1, 0, 0, 0, 0, 0, 0, nullptr, nullptr, T_, 2, b1, nullptr, 1.f);

    // FFN2: y = h + ff1 @ W2.T + b2 -> d_out
    gemm_tf32<128, 128><<<dim3(D_ / 128, T_ / 128, 1), 256, GEMM_SMEM>>>(
        p_ff1, W2, out, D_, FF_ * D_, FF_ * D_, FF_ * D_, D_,
        1, 0, 0, 0, 0, 0, 0, nullptr, nullptr, T_, 3, b2, p_h, 1.f);

    lb_kernel<<<1, 256>>>(out, out_size);
}

// round 4
// speedup vs baseline: 1.4650x; 1.4437x over previous
#include <cuda_runtime.h>
#include <cuda_fp16.h>
#include <math.h>
#include <stdint.h>

// ---------------- problem constants ----------------
#define B_   4
#define N_   1024
#define D_   1024
#define H_   16
#define E_   12
#define KTOP 2
#define FF_  4
#define HD_  64
#define T_   (B_*N_)
#define A_   (T_*KTOP)
#define TD   ((long long)T_*D_)

// ---------------- static device scratch ----------------
__device__ float  g_xn   [T_*D_];
__device__ __half g_xn_h [T_*D_];
__device__ float  g_probs[T_*E_];
__device__ int    g_topi [T_*KTOP];
__device__ float  g_topw [T_*KTOP];
__device__ int    g_cnt  [E_];
__device__ int    g_off  [E_+1];
__device__ int    g_ctr  [E_];
__device__ int    g_tok  [A_];
__device__ int    g_aidx [T_*KTOP];
__device__ float  g_projQ[A_*D_];
__device__ float  g_projK[A_*D_];
__device__ float  g_projV[A_*D_];
__device__ float  g_q    [T_*D_];
__device__ float  g_k    [T_*D_];
__device__ float  g_v    [T_*D_];
__device__ __half g_att_h[T_*D_];
__device__ float  g_o    [T_*D_];
__device__ float  g_h    [T_*D_];
__device__ __half g_hn_h [T_*D_];
__device__ __half g_ff1_h[T_*FF_*D_];
// half weight shadows
__device__ __half g_Wq_h[E_*D_*D_];
__device__ __half g_Wk_h[E_*D_*D_];
__device__ __half g_Wv_h[E_*D_*D_];
__device__ __half g_Wo_h[E_*D_*D_];
__device__ __half g_W1_h[FF_*D_*D_];
__device__ __half g_W2_h[FF_*D_*D_];

// ---------------- PTX helpers ----------------
__device__ __forceinline__ uint32_t smem_u32(const void* p) {
    uint32_t a;
    asm("{ .reg .u64 t; cvta.to.shared.u64 t, %1; cvt.u32.u64 %0, t; }"
        : "=r"(a) : "l"(p));
    return a;
}
__device__ __forceinline__ void cp_async16s(uint32_t s, const void* g, int sz) {
    asm volatile("cp.async.cg.shared.global [%0], [%1], 16, %2;\n"
                 :: "r"(s), "l"(g), "r"(sz));
}
__device__ __forceinline__ void cp_async16(void* s, const void* g, int sz) {
    cp_async16s(smem_u32(s), g, sz);
}
__device__ __forceinline__ void cp_commit() {
    asm volatile("cp.async.commit_group;\n");
}
template<int NN>
__device__ __forceinline__ void cp_wait() {
    asm volatile("cp.async.wait_group %0;\n" :: "n"(NN));
}
#define SWZ(o) ((o) ^ (((o) >> 3) & 0x70))

#define LDSM_X4(r0, r1, r2, r3, addr) \
    asm volatile("ldmatrix.sync.aligned.m8n8.x4.shared.b16 {%0,%1,%2,%3}, [%4];" \
        : "=r"(r0), "=r"(r1), "=r"(r2), "=r"(r3) : "r"(addr))

__device__ __forceinline__ void mma_f16(float c[4],
        uint32_t a0, uint32_t a1, uint32_t a2, uint32_t a3,
        uint32_t b0, uint32_t b1) {
    asm volatile(
        "mma.sync.aligned.m16n8k16.row.col.f32.f16.f16.f32 "
        "{%0,%1,%2,%3}, {%4,%5,%6,%7}, {%8,%9}, {%0,%1,%2,%3};"
        : "+f"(c[0]), "+f"(c[1]), "+f"(c[2]), "+f"(c[3])
        : "r"(a0), "r"(a1), "r"(a2), "r"(a3), "r"(b0), "r"(b1));
}

// legacy tf32 mma (flash attention)
__device__ __forceinline__ void mma_tf32(float c[4],
        float a0, float a1, float a2, float a3, float b0, float b1) {
    asm volatile(
        "mma.sync.aligned.m16n8k8.row.col.f32.tf32.tf32.f32 "
        "{%0,%1,%2,%3}, {%4,%5,%6,%7}, {%8,%9}, {%0,%1,%2,%3};"
        : "+f"(c[0]), "+f"(c[1]), "+f"(c[2]), "+f"(c[3])
        : "r"(__float_as_uint(a0)), "r"(__float_as_uint(a1)),
          "r"(__float_as_uint(a2)), "r"(__float_as_uint(a3)),
          "r"(__float_as_uint(b0)), "r"(__float_as_uint(b1)));
}
__device__ __forceinline__ float f2tf_rna(float f) {
    uint32_t u;
    asm("cvt.rna.tf32.f32 %0, %1;" : "=r"(u) : "f"(f));
    return __uint_as_float(u);
}
__device__ __forceinline__ float fast_exp2(float x) {
    float y;
    asm("ex2.approx.f32 %0, %1;" : "=f"(y) : "f"(x));
    return y;
}
__device__ __forceinline__ float gelu_tanh(float x) {
    float x3 = x * x * x;
    return 0.5f * x * (1.0f + tanhf(0.7978845608028654f * (x + 0.044715f * x3)));
}
__device__ __forceinline__ float block_reduce_sum(float v, float* sh) {
    int tid = threadIdx.x;
    #pragma unroll
    for (int o = 16; o; o >>= 1) v += __shfl_xor_sync(0xffffffffu, v, o);
    if ((tid & 31) == 0) sh[tid >> 5] = v;
    __syncthreads();
    if (tid < 32) {
        v = (tid < (int)(blockDim.x >> 5)) ? sh[tid] : 0.0f;
        #pragma unroll
        for (int o = 16; o; o >>= 1) v += __shfl_xor_sync(0xffffffffu, v, o);
        if (tid == 0) sh[0] = v;
    }
    __syncthreads();
    float r = sh[0];
    __syncthreads();
    return r;
}

// ================= fp16 HMMA GEMM =================
// C[m,n] = sum_k A[m,k]*B[n,k] (half inputs, f32 accum). 128x128 tiles,
// BK=64 (128B rows, SW128), 3-stage cp.async, ldmatrix fragments.
// Optional grouped row gather; optional z-batch for expert weights.
#define GH_STAGES 3
#define GH_STAGE_BYTES 32768       // A 16KB + B 16KB
#define GH_SMEM (GH_STAGES*GH_STAGE_BYTES)   // 98304

__global__ void __launch_bounds__(256)
gemm_h(const __half* __restrict__ A, const __half* __restrict__ Bw,
       float* __restrict__ C, __half* __restrict__ Ch,
       int K, int lda, int ldb, int ldc,
       long long bzoff,
       const int* __restrict__ seg_off, const int* __restrict__ tok,
       int Mfull, int epi,
       const float* __restrict__ bias, const float* __restrict__ resid) {
    extern __shared__ char smem[];
    uint32_t sb = smem_u32(smem);
    int tid = threadIdx.x, lane = tid & 31, warp = tid >> 5;
    int gid = lane >> 2, tig = lane & 3;
    int wm = warp & 1, wn = warp >> 1;      // 2 x 4 warps -> 64 x 32 per warp

    int z = blockIdx.z;
    const __half* Bb = Bw + (long long)z * bzoff;
    float* Cb = C;
    __half* Chb = Ch;

    int Mseg = Mfull;
    const int* grows = nullptr;
    if (seg_off) {
        int s = seg_off[z];
        Mseg  = seg_off[z + 1] - s;
        grows = tok + s;
        Cb = C + (long long)s * ldc;
    }
    int m0 = blockIdx.y * 128;
    if (m0 >= Mseg) return;
    int n0 = blockIdx.x * 128;

    float acc[4][4][4];
    #pragma unroll
    for (int i = 0; i < 4; i++)
        #pragma unroll
        for (int j = 0; j < 4; j++)
            #pragma unroll
            for (int u = 0; u < 4; u++) acc[i][j][u] = 0.0f;

    int nk = K / 64;

    auto issue = [&](int it) {
        int st = it % GH_STAGES;
        uint32_t abase = sb + st * GH_STAGE_BYTES;
        uint32_t bbase = abase + 16384;
        int k0 = it * 64;
        #pragma unroll
        for (int c = 0; c < 4; c++) {       // A: 1024 16B chunks
            int ch = tid + 256 * c;
            int row = ch >> 3, kc = ch & 7;
            int gm = m0 + row;
            uint32_t dst = abase + SWZ((uint32_t)(row * 128 + kc * 16));
            const __half* src = A;
            int sz = 0;
            if (gm < Mseg) {
                long long rr = grows ? (long long)grows[gm] : (long long)gm;
                src = A + rr * (long long)lda + k0 + kc * 8;
                sz = 16;
            }
            cp_async16s(dst, src, sz);
        }
        #pragma unroll
        for (int c = 0; c < 4; c++) {       // B
            int ch = tid + 256 * c;
            int row = ch >> 3, kc = ch & 7;
            uint32_t dst = bbase + SWZ((uint32_t)(row * 128 + kc * 16));
            cp_async16s(dst, Bb + (long long)(n0 + row) * ldb + k0 + kc * 8, 16);
        }
        cp_commit();
    };

    issue(0);
    if (nk > 1) issue(1);

    for (int it = 0; it < nk; it++) {
        if (it < nk - 1) cp_wait<1>(); else cp_wait<0>();
        __syncthreads();
        if (it + 2 < nk) issue(it + 2);

        int st = it % GH_STAGES;
        uint32_t abase = sb + st * GH_STAGE_BYTES;
        uint32_t bbase = abase + 16384;

        #pragma unroll
        for (int ks = 0; ks < 4; ks++) {    // 4 k16 steps
            uint32_t af[4][4];
            #pragma unroll
            for (int i = 0; i < 4; i++) {
                int row = wm * 64 + i * 16 + (lane & 15);
                uint32_t addr = abase +
                    SWZ((uint32_t)(row * 128 + ks * 32 + (lane >> 4) * 16));
                LDSM_X4(af[i][0], af[i][1], af[i][2], af[i][3], addr);
            }
            uint32_t bf[4][2];
            #pragma unroll
            for (int jp = 0; jp < 2; jp++) {
                int nrow = wn * 32 + jp * 16 + (lane & 15);
                uint32_t addr = bbase +
                    SWZ((uint32_t)(nrow * 128 + ks * 32 + (lane >> 4) * 16));
                uint32_t r0, r1, r2, r3;
                LDSM_X4(r0, r1, r2, r3, addr);
                bf[jp * 2][0] = r0; bf[jp * 2 + 1][0] = r1;
                bf[jp * 2][1] = r2; bf[jp * 2 + 1][1] = r3;
            }
            #pragma unroll
            for (int i = 0; i < 4; i++)
                #pragma unroll
                for (int j = 0; j < 4; j++)
                    mma_f16(acc[i][j], af[i][0], af[i][1], af[i][2], af[i][3],
                            bf[j][0], bf[j][1]);
        }
        __syncthreads();
    }

    // epilogue
    #pragma unroll
    for (int i = 0; i < 4; i++)
        #pragma unroll
        for (int j = 0; j < 4; j++)
            #pragma unroll
            for (int h2 = 0; h2 < 2; h2++) {
                int r  = wm * 64 + i * 16 + gid + h2 * 8;
                int gm = m0 + r;
                if (gm >= Mseg) continue;
                int c  = wn * 32 + j * 8 + tig * 2;
                int gn = n0 + c;
                float v0 = acc[i][j][h2 * 2 + 0];
                float v1 = acc[i][j][h2 * 2 + 1];
                long long off = (long long)gm * ldc + gn;
                if (epi == 2) {
                    v0 = gelu_tanh(v0 + bias[gn]);
                    v1 = gelu_tanh(v1 + bias[gn + 1]);
                    *reinterpret_cast<__half2*>(Chb + off) =
                        __floats2half2_rn(v0, v1);
                } else if (epi == 3) {
                    float2 rr = *reinterpret_cast<const float2*>(resid + off);
                    v0 = v0 + bias[gn] + rr.x;
                    v1 = v1 + bias[gn + 1] + rr.y;
                    *reinterpret_cast<float2*>(Cb + off) = make_float2(v0, v1);
                } else {
                    *reinterpret_cast<float2*>(Cb + off) = make_float2(v0, v1);
                }
            }
}

// ================= flash attention (tf32 mma, f32 in, half out) =================
#define FA_KS_STRIDE 68
#define FA_VS_STRIDE 72
#define FA_PS_STRIDE 132
#define FA_SMEM_FLOATS (128*FA_KS_STRIDE + 128*FA_VS_STRIDE + 8*16*FA_PS_STRIDE)

__global__ void __launch_bounds__(256)
flash_attn_kernel() {
    extern __shared__ float sm[];
    float* Ks = sm;
    float* Vs = sm + 128 * FA_KS_STRIDE;
    float* Ps = Vs + 128 * FA_VS_STRIDE;

    int bh = blockIdx.y;
    int b = bh >> 4, h = bh & 15;
    int q0 = blockIdx.x * 128;
    int tid = threadIdx.x, lane = tid & 31, w = tid >> 5;
    int gid = lane >> 2, tig = lane & 3;

    const float* Qg = g_q + ((long long)(b * N_ + q0 + w * 16)) * D_ + h * HD_;
    float qf[8][4];
    #pragma unroll
    for (int kf = 0; kf < 8; kf++) {
        const float* qp = Qg + kf * 8;
        qf[kf][0] = f2tf_rna(qp[(long long)gid * D_ + tig]);
        qf[kf][1] = f2tf_rna(qp[(long long)(gid + 8) * D_ + tig]);
        qf[kf][2] = f2tf_rna(qp[(long long)gid * D_ + tig + 4]);
        qf[kf][3] = f2tf_rna(qp[(long long)(gid + 8) * D_ + tig + 4]);
    }

    float of[8][4];
    #pragma unroll
    for (int j = 0; j < 8; j++)
        #pragma unroll
        for (int u = 0; u < 4; u++) of[j][u] = 0.0f;

    float M0 = -1e30f, M1 = -1e30f, L0 = 0.f, L1 = 0.f;
    const float CE = 0.125f * 1.4426950408889634f;
    float* Pw = Ps + w * 16 * FA_PS_STRIDE;

    for (int kv0 = 0; kv0 < N_; kv0 += 128) {
        const float* Kg = g_k + ((long long)(b * N_ + kv0)) * D_ + h * HD_;
        const float* Vg = g_v + ((long long)(b * N_ + kv0)) * D_ + h * HD_;
        #pragma unroll
        for (int p = 0; p < 8; p++) {
            int chunk = tid + 256 * p;
            int r = chunk >> 4, c = (chunk & 15) * 4;
            cp_async16(&Ks[r * FA_KS_STRIDE + c], Kg + (long long)r * D_ + c, 16);
            cp_async16(&Vs[r * FA_VS_STRIDE + c], Vg + (long long)r * D_ + c, 16);
        }
        cp_commit();
        cp_wait<0>();
        __syncthreads();

        float sf[16][4];
        #pragma unroll
        for (int j = 0; j < 16; j++)
            #pragma unroll
            for (int u = 0; u < 4; u++) sf[j][u] = 0.0f;
        #pragma unroll
        for (int kf = 0; kf < 8; kf++) {
            int ko = kf * 8;
            #pragma unroll
            for (int j = 0; j < 16; j++) {
                int n = j * 8 + gid;
                float b0 = Ks[n * FA_KS_STRIDE + ko + tig];
                float b1 = Ks[n * FA_KS_STRIDE + ko + tig + 4];
                mma_tf32(sf[j], qf[kf][0], qf[kf][1], qf[kf][2], qf[kf][3], b0, b1);
            }
        }

        float mx0 = -1e30f, mx1 = -1e30f;
        #pragma unroll
        for (int j = 0; j < 16; j++) {
            mx0 = fmaxf(mx0, fmaxf(sf[j][0], sf[j][1]));
            mx1 = fmaxf(mx1, fmaxf(sf[j][2], sf[j][3]));
        }
        mx0 = fmaxf(mx0, __shfl_xor_sync(0xffffffffu, mx0, 1));
        mx0 = fmaxf(mx0, __shfl_xor_sync(0xffffffffu, mx0, 2));
        mx1 = fmaxf(mx1, __shfl_xor_sync(0xffffffffu, mx1, 1));
        mx1 = fmaxf(mx1, __shfl_xor_sync(0xffffffffu, mx1, 2));
        float nM0 = fmaxf(M0, mx0), nM1 = fmaxf(M1, mx1);
        float corr0 = fast_exp2(CE * (M0 - nM0));
        float corr1 = fast_exp2(CE * (M1 - nM1));

        float s0 = 0.f, s1 = 0.f;
        #pragma unroll
        for (int j = 0; j < 16; j++) {
            float p0 = fast_exp2(CE * (sf[j][0] - nM0));
            float p1 = fast_exp2(CE * (sf[j][1] - nM0));
            float p2 = fast_exp2(CE * (sf[j][2] - nM1));
            float p3 = fast_exp2(CE * (sf[j][3] - nM1));
            s0 += p0 + p1; s1 += p2 + p3;
            *reinterpret_cast<float2*>(&Pw[gid * FA_PS_STRIDE + j * 8 + tig * 2]) =
                make_float2(p0, p1);
            *reinterpret_cast<float2*>(&Pw[(gid + 8) * FA_PS_STRIDE + j * 8 + tig * 2]) =
                make_float2(p2, p3);
        }
        s0 += __shfl_xor_sync(0xffffffffu, s0, 1);
        s0 += __shfl_xor_sync(0xffffffffu, s0, 2);
        s1 += __shfl_xor_sync(0xffffffffu, s1, 1);
        s1 += __shfl_xor_sync(0xffffffffu, s1, 2);
        L0 = L0 * corr0 + s0;
        L1 = L1 * corr1 + s1;
        M0 = nM0; M1 = nM1;

        #pragma unroll
        for (int j = 0; j < 8; j++) {
            of[j][0] *= corr0; of[j][1] *= corr0;
            of[j][2] *= corr1; of[j][3] *= corr1;
        }
        __syncwarp();

        #pragma unroll
        for (int k2 = 0; k2 < 16; k2++) {
            int ko = k2 * 8;
            float a0 = Pw[gid * FA_PS_STRIDE + ko + tig];
            float a1 = Pw[(gid + 8) * FA_PS_STRIDE + ko + tig];
            float a2 = Pw[gid * FA_PS_STRIDE + ko + tig + 4];
            float a3 = Pw[(gid + 8) * FA_PS_STRIDE + ko + tig + 4];
            #pragma unroll
            for (int j = 0; j < 8; j++) {
                float b0 = Vs[(ko + tig) * FA_VS_STRIDE + j * 8 + gid];
                float b1 = Vs[(ko + tig + 4) * FA_VS_STRIDE + j * 8 + gid];
                mma_tf32(of[j], a0, a1, a2, a3, b0, b1);
            }
        }
        __syncthreads();
    }

    float i0 = 1.0f / L0, i1 = 1.0f / L1;
    __half* Og = g_att_h + ((long long)(b * N_ + q0 + w * 16)) * D_ + h * HD_;
    #pragma unroll
    for (int j = 0; j < 8; j++) {
        *reinterpret_cast<__half2*>(&Og[(long long)gid * D_ + j * 8 + tig * 2]) =
            __floats2half2_rn(of[j][0] * i0, of[j][1] * i0);
        *reinterpret_cast<__half2*>(&Og[(long long)(gid + 8) * D_ + j * 8 + tig * 2]) =
            __floats2half2_rn(of[j][2] * i1, of[j][3] * i1);
    }
}

// ---------------- small kernels ----------------
__global__ void f2h_kernel(const float* __restrict__ src, __half* __restrict__ dst,
                           int n4) {
    int i = blockIdx.x * blockDim.x + threadIdx.x;
    if (i >= n4) return;
    float4 v = reinterpret_cast<const float4*>(src)[i];
    __half2 h0 = __floats2half2_rn(v.x, v.y);
    __half2 h1 = __floats2half2_rn(v.z, v.w);
    reinterpret_cast<__half2*>(dst)[i * 2 + 0] = h0;
    reinterpret_cast<__half2*>(dst)[i * 2 + 1] = h1;
}

// LayerNorm: optional add (residual), f32 out, half out, raw-sum out, counter init
__global__ void ln_kernel(const float* __restrict__ x, const float* __restrict__ add,
                          const float* __restrict__ g, const float* __restrict__ b,
                          float* __restrict__ out, __half* __restrict__ out_h,
                          float* __restrict__ hout, int do_init) {
    __shared__ float sh[33];
    long long row = blockIdx.x;
    int tid = threadIdx.x;
    if (do_init && blockIdx.x == 0 && tid < E_) g_cnt[tid] = 0;
    float v[4];
    #pragma unroll
    for (int i = 0; i < 4; i++) {
        int c = tid + 256 * i;
        v[i] = x[row * D_ + c];
        if (add)  v[i] += add[row * D_ + c];
        if (hout) hout[row * D_ + c] = v[i];
    }
    float s = block_reduce_sum(v[0] + v[1] + v[2] + v[3], sh);
    float m = s * (1.0f / D_);
    float q = 0.f;
    #pragma unroll
    for (int i = 0; i < 4; i++) { float d = v[i] - m; q += d * d; }
    q = block_reduce_sum(q, sh);
    float rstd = rsqrtf(q * (1.0f / D_) + 1e-5f);
    #pragma unroll
    for (int i = 0; i < 4; i++) {
        int c = tid + 256 * i;
        float r = (v[i] - m) * rstd * g[c] + b[c];
        if (out)   out[row * D_ + c] = r;
        if (out_h) out_h[row * D_ + c] = __float2half(r);
    }
}

__global__ void router_kernel(const float* __restrict__ Wr) {
    int warp = (blockIdx.x * blockDim.x + threadIdx.x) >> 5;
    int lane = threadIdx.x & 31;
    if (warp >= T_) return;
    const float* xr = g_xn + (long long)warp * D_;
    float acc[E_];
    #pragma unroll
    for (int e = 0; e < E_; e++) acc[e] = 0.f;
    for (int i = lane; i < D_; i += 32) {
        float xv = xr[i];
        #pragma unroll
        for (int e = 0; e < E_; e++) acc[e] += xv * Wr[e * D_ + i];
    }
    #pragma unroll
    for (int e = 0; e < E_; e++)
        #pragma unroll
        for (int o = 16; o; o >>= 1) acc[e] += __shfl_xor_sync(0xffffffffu, acc[e], o);
    if (lane == 0) {
        float mx = acc[0];
        #pragma unroll
        for (int e = 1; e < E_; e++) mx = fmaxf(mx, acc[e]);
        float p[E_], s = 0.f;
        #pragma unroll
        for (int e = 0; e < E_; e++) { p[e] = expf(acc[e] - mx); s += p[e]; }
        float inv = 1.0f / s;
        #pragma unroll
        for (int e = 0; e < E_; e++) { p[e] *= inv; g_probs[warp * E_ + e] = p[e]; }
        int i0 = 0;
        #pragma unroll
        for (int e = 1; e < E_; e++) if (p[e] > p[i0]) i0 = e;
        int i1 = (i0 == 0) ? 1 : 0;
        #pragma unroll
        for (int e = 0; e < E_; e++) if (e != i0 && p[e] > p[i1]) i1 = e;
        float v0 = p[i0], v1 = p[i1];
        float wsum = v0 + v1 + 1e-6f;
        g_topi[warp * 2 + 0] = i0;
        g_topi[warp * 2 + 1] = i1;
        g_topw[warp * 2 + 0] = v0 / wsum;
        g_topw[warp * 2 + 1] = v1 / wsum;
        atomicAdd(&g_cnt[i0], 1);
        atomicAdd(&g_cnt[i1], 1);
    }
}

// merged scan + scatter (single block)
__global__ void scan_scatter_kernel() {
    int tid = threadIdx.x;
    if (tid == 0) {
        int s = 0;
        for (int e = 0; e < E_; e++) { g_off[e] = s; s += g_cnt[e]; g_ctr[e] = 0; }
        g_off[E_] = s;
    }
    __syncthreads();
    for (int idx = tid; idx < A_; idx += 256) {
        int e = g_topi[idx];
        int pos = g_off[e] + atomicAdd(&g_ctr[e], 1);
        g_tok[pos]  = idx >> 1;
        g_aidx[idx] = pos;
    }
}

// combine Q, K, V from three proj buffers in one pass
__global__ void combine_qkv_kernel() {
    long long t = blockIdx.x;
    int tid = threadIdx.x;
    int a0 = g_aidx[t * 2 + 0], a1 = g_aidx[t * 2 + 1];
    float w0 = g_topw[t * 2 + 0], w1 = g_topw[t * 2 + 1];
    long long r0 = (long long)a0 * D_, r1 = (long long)a1 * D_;
    #pragma unroll
    for (int i = 0; i < 4; i++) {
        int c = tid + 256 * i;
        g_q[t * D_ + c] = w0 * g_projQ[r0 + c] + w1 * g_projQ[r1 + c];
        g_k[t * D_ + c] = w0 * g_projK[r0 + c] + w1 * g_projK[r1 + c];
        g_v[t * D_ + c] = w0 * g_projV[r0 + c] + w1 * g_projV[r1 + c];
    }
}

__global__ void combine_o_kernel() {
    long long t = blockIdx.x;
    int tid = threadIdx.x;
    int a0 = g_aidx[t * 2 + 0], a1 = g_aidx[t * 2 + 1];
    float w0 = g_topw[t * 2 + 0], w1 = g_topw[t * 2 + 1];
    long long r0 = (long long)a0 * D_, r1 = (long long)a1 * D_;
    #pragma unroll
    for (int i = 0; i < 4; i++) {
        int c = tid + 256 * i;
        g_o[t * D_ + c] = w0 * g_projQ[r0 + c] + w1 * g_projQ[r1 + c];
    }
}

__global__ void lb_kernel(float* __restrict__ out, int out_size) {
    __shared__ float sh[256];
    int tid = threadIdx.x;
    float pl[E_];
    #pragma unroll
    for (int e = 0; e < E_; e++) pl[e] = 0.f;
    for (int t = tid; t < T_; t += 256)
        #pragma unroll
        for (int e = 0; e < E_; e++) pl[e] += g_probs[t * E_ + e];
    float pe[E_];
    for (int e = 0; e < E_; e++) {
        sh[tid] = pl[e];
        __syncthreads();
        for (int o = 128; o; o >>= 1) {
            if (tid < o) sh[tid] += sh[tid + o];
            __syncthreads();
        }
        pe[e] = sh[0];
        __syncthreads();
    }
    if (tid == 0) {
        float lb = 0.f;
        float denom = (float)A_ + 1e-6f;
        for (int e = 0; e < E_; e++)
            lb += ((float)g_cnt[e] / denom) * pe[e];
        lb *= (float)E_;
        if (out_size > (int)TD) out[TD] = lb;
    }
}

// ---------------- host launch ----------------
extern "C" void kernel_launch(void* const* d_in, const int* in_sizes, int n_in,
                              void* d_out, int out_size) {
    const float* x   = (const float*)d_in[0];
    const float* Wr  = (const float*)d_in[1];
    const float* Wq  = (const float*)d_in[2];
    const float* Wk  = (const float*)d_in[3];
    const float* Wv  = (const float*)d_in[4];
    const float* Wo  = (const float*)d_in[5];
    const float* W1  = (const float*)d_in[6];
    const float* b1  = (const float*)d_in[7];
    const float* W2  = (const float*)d_in[8];
    const float* b2  = (const float*)d_in[9];
    const float* g1  = (const float*)d_in[10];
    const float* be1 = (const float*)d_in[11];
    const float* g2  = (const float*)d_in[12];
    const float* be2 = (const float*)d_in[13];
    float* out = (float*)d_out;

    float  *p_xn, *p_projQ, *p_projK, *p_projV, *p_h;
    __half *p_xn_h, *p_att_h, *p_hn_h, *p_ff1_h;
    __half *p_Wq_h, *p_Wk_h, *p_Wv_h, *p_Wo_h, *p_W1_h, *p_W2_h;
    int *p_off, *p_tok;
    cudaGetSymbolAddress((void**)&p_xn,   g_xn);
    cudaGetSymbolAddress((void**)&p_xn_h, g_xn_h);
    cudaGetSymbolAddress((void**)&p_projQ,g_projQ);
    cudaGetSymbolAddress((void**)&p_projK,g_projK);
    cudaGetSymbolAddress((void**)&p_projV,g_projV);
    cudaGetSymbolAddress((void**)&p_att_h,g_att_h);
    cudaGetSymbolAddress((void**)&p_h,    g_h);
    cudaGetSymbolAddress((void**)&p_hn_h, g_hn_h);
    cudaGetSymbolAddress((void**)&p_ff1_h,g_ff1_h);
    cudaGetSymbolAddress((void**)&p_Wq_h, g_Wq_h);
    cudaGetSymbolAddress((void**)&p_Wk_h, g_Wk_h);
    cudaGetSymbolAddress((void**)&p_Wv_h, g_Wv_h);
    cudaGetSymbolAddress((void**)&p_Wo_h, g_Wo_h);
    cudaGetSymbolAddress((void**)&p_W1_h, g_W1_h);
    cudaGetSymbolAddress((void**)&p_W2_h, g_W2_h);
    cudaGetSymbolAddress((void**)&p_off,  g_off);
    cudaGetSymbolAddress((void**)&p_tok,  g_tok);

    float* p_o; cudaGetSymbolAddress((void**)&p_o, g_o);

    const long long EDD = (long long)E_ * D_ * D_;
    const long long DD  = (long long)D_ * D_;
    const int FA_SMEM = FA_SMEM_FLOATS * 4;
    cudaFuncSetAttribute(gemm_h,
                         cudaFuncAttributeMaxDynamicSharedMemorySize, GH_SMEM);
    cudaFuncSetAttribute(flash_attn_kernel,
                         cudaFuncAttributeMaxDynamicSharedMemorySize, FA_SMEM);

    // weight conversions (independent of everything else)
    {
        int n4 = (int)(EDD / 4);
        int blk = (n4 + 255) / 256;
        f2h_kernel<<<blk, 256>>>(Wq, p_Wq_h, n4);
        f2h_kernel<<<blk, 256>>>(Wk, p_Wk_h, n4);
        f2h_kernel<<<blk, 256>>>(Wv, p_Wv_h, n4);
        f2h_kernel<<<blk, 256>>>(Wo, p_Wo_h, n4);
        int nf = (int)((long long)FF_ * D_ * D_ / 4);
        int blkf = (nf + 255) / 256;
        f2h_kernel<<<blkf, 256>>>(W1, p_W1_h, nf);
        f2h_kernel<<<blkf, 256>>>(W2, p_W2_h, nf);
    }

    // LN1 (+ counter init), router, scan+scatter
    ln_kernel<<<T_, 256>>>(x, nullptr, g1, be1, p_xn, p_xn_h, nullptr, 1);
    router_kernel<<<T_ / 8, 256>>>(Wr);
    scan_scatter_kernel<<<1, 256>>>();

    // grouped GEMMs Q, K, V (fp16), then one combine
    dim3 ggrid(D_ / 128, A_ / 128, E_);
    gemm_h<<<ggrid, 256, GH_SMEM>>>(p_xn_h, p_Wq_h, p_projQ, nullptr,
        D_, D_, D_, D_, DD, p_off, p_tok, A_, 0, nullptr, nullptr);
    gemm_h<<<ggrid, 256, GH_SMEM>>>(p_xn_h, p_Wk_h, p_projK, nullptr,
        D_, D_, D_, D_, DD, p_off, p_tok, A_, 0, nullptr, nullptr);
    gemm_h<<<ggrid, 256, GH_SMEM>>>(p_xn_h, p_Wv_h, p_projV, nullptr,
        D_, D_, D_, D_, DD, p_off, p_tok, A_, 0, nullptr, nullptr);
    combine_qkv_kernel<<<T_, 256>>>();

    // fused attention -> att_h
    flash_attn_kernel<<<dim3(N_ / 128, B_ * H_), 256, FA_SMEM>>>();

    // grouped O projection + combine
    gemm_h<<<ggrid, 256, GH_SMEM>>>(p_att_h, p_Wo_h, p_projQ, nullptr,
        D_, D_, D_, D_, DD, p_off, p_tok, A_, 0, nullptr, nullptr);
    combine_o_kernel<<<T_, 256>>>();

    // h = x + o ; hn = LN2(h) -> half
    ln_kernel<<<T_, 256>>>(x, p_o, g2, be2, nullptr, p_hn_h, p_h, 0);

    // FFN1: ff1_h = gelu(hn @ W1.T + b1)
    gemm_h<<<dim3(FF_ * D_ / 128, T_ / 128, 1), 256, GH_SMEM>>>(
        p_hn_h, p_W1_h, nullptr, p_ff1_h,
        D_, D_, D_, FF_ * D_, 0, nullptr, nullptr, T_, 2, b1, nullptr);

    // FFN2: y = h + ff1 @ W2.T + b2 -> d_out
    gemm_h<<<dim3(D_ / 128, T_ / 128, 1), 256, GH_SMEM>>>(
        p_ff1_h, p_W2_h, out, nullptr,
        FF_ * D_, FF_ * D_, FF_ * D_, D_, 0, nullptr, nullptr, T_, 3, b2, p_h);

    lb_kernel<<<1, 256>>>(out, out_size);
}

// round 6
// speedup vs baseline: 2.5901x; 1.7680x over previous
#include <cuda_runtime.h>
#include <cuda_fp16.h>
#include <math.h>
#include <stdint.h>

// ---------------- problem constants ----------------
#define B_   4
#define N_   1024
#define D_   1024
#define H_   16
#define E_   12
#define KTOP 2
#define FF_  4
#define HD_  64
#define T_   (B_*N_)
#define A_   (T_*KTOP)
#define TD   ((long long)T_*D_)

// ---------------- static device scratch ----------------
__device__ float  g_xn   [T_*D_];
__device__ __half g_xn_h [T_*D_];
__device__ float  g_probs[T_*E_];
__device__ int    g_topi [T_*KTOP];
__device__ float  g_topw [T_*KTOP];
__device__ int    g_cnt  [E_];
__device__ int    g_off  [E_+1];
__device__ int    g_ctr  [E_];
__device__ int    g_tok  [A_];
__device__ int    g_aidx [T_*KTOP];
__device__ __half g_projQKV[3LL*A_*D_];   // Q | K | V slots; O reuses slot 0
__device__ __half g_q_h  [T_*D_];
__device__ __half g_k_h  [T_*D_];
__device__ __half g_v_h  [T_*D_];
__device__ __half g_att_h[T_*D_];
__device__ float  g_o    [T_*D_];
__device__ float  g_h    [T_*D_];
__device__ __half g_hn_h [T_*D_];
__device__ __half g_ff1_h[T_*FF_*D_];
// half weight shadows
__device__ __half g_Wqkv_h[3LL*E_*D_*D_];
__device__ __half g_Wo_h  [(long long)E_*D_*D_];
__device__ __half g_W1_h  [(long long)FF_*D_*D_];
__device__ __half g_W2_h  [(long long)FF_*D_*D_];

// ---------------- PTX helpers ----------------
__device__ __forceinline__ uint32_t smem_u32(const void* p) {
    uint32_t a;
    asm("{ .reg .u64 t; cvta.to.shared.u64 t, %1; cvt.u32.u64 %0, t; }"
        : "=r"(a) : "l"(p));
    return a;
}
__device__ __forceinline__ void cp_async16s(uint32_t s, const void* g, int sz) {
    asm volatile("cp.async.cg.shared.global [%0], [%1], 16, %2;\n"
                 :: "r"(s), "l"(g), "r"(sz));
}
__device__ __forceinline__ void cp_commit() {
    asm volatile("cp.async.commit_group;\n");
}
template<int NN>
__device__ __forceinline__ void cp_wait() {
    asm volatile("cp.async.wait_group %0;\n" :: "n"(NN));
}
#define SWZ(o) ((o) ^ (((o) >> 3) & 0x70))

#define LDSM_X4(r0, r1, r2, r3, addr) \
    asm volatile("ldmatrix.sync.aligned.m8n8.x4.shared.b16 {%0,%1,%2,%3}, [%4];" \
        : "=r"(r0), "=r"(r1), "=r"(r2), "=r"(r3) : "r"(addr))
#define LDSM_X4_T(r0, r1, r2, r3, addr) \
    asm volatile("ldmatrix.sync.aligned.m8n8.x4.trans.shared.b16 {%0,%1,%2,%3}, [%4];" \
        : "=r"(r0), "=r"(r1), "=r"(r2), "=r"(r3) : "r"(addr))

__device__ __forceinline__ void mma_f16(float c[4],
        uint32_t a0, uint32_t a1, uint32_t a2, uint32_t a3,
        uint32_t b0, uint32_t b1) {
    asm volatile(
        "mma.sync.aligned.m16n8k16.row.col.f32.f16.f16.f32 "
        "{%0,%1,%2,%3}, {%4,%5,%6,%7}, {%8,%9}, {%0,%1,%2,%3};"
        : "+f"(c[0]), "+f"(c[1]), "+f"(c[2]), "+f"(c[3])
        : "r"(a0), "r"(a1), "r"(a2), "r"(a3), "r"(b0), "r"(b1));
}
__device__ __forceinline__ float fast_exp2(float x) {
    float y;
    asm("ex2.approx.f32 %0, %1;" : "=f"(y) : "f"(x));
    return y;
}
__device__ __forceinline__ float gelu_tanh(float x) {
    float x3 = x * x * x;
    return 0.5f * x * (1.0f + tanhf(0.7978845608028654f * (x + 0.044715f * x3)));
}
__device__ __forceinline__ float block_reduce_sum(float v, float* sh) {
    int tid = threadIdx.x;
    #pragma unroll
    for (int o = 16; o; o >>= 1) v += __shfl_xor_sync(0xffffffffu, v, o);
    if ((tid & 31) == 0) sh[tid >> 5] = v;
    __syncthreads();
    if (tid < 32) {
        v = (tid < (int)(blockDim.x >> 5)) ? sh[tid] : 0.0f;
        #pragma unroll
        for (int o = 16; o; o >>= 1) v += __shfl_xor_sync(0xffffffffu, v, o);
        if (tid == 0) sh[0] = v;
    }
    __syncthreads();
    float r = sh[0];
    __syncthreads();
    return r;
}

// ================= fp16 HMMA GEMM =================
// C[m,n] = sum_k A[m,k]*B[n,k] (half in, f32 accum). 128x128 tiles, BK=64,
// SW128, 3-stage cp.async, ldmatrix. Optional row gather; z = z1*zdiv + z2,
// B += z1*bz1 + z2*bz2, Chalf += z1*cz1, expert = z2.
#define GH_STAGES 3
#define GH_STAGE_BYTES 32768
#define GH_SMEM (GH_STAGES*GH_STAGE_BYTES)

__global__ void __launch_bounds__(256)
gemm_h(const __half* __restrict__ A, const __half* __restrict__ Bw,
       float* __restrict__ C, __half* __restrict__ Ch,
       int K, int lda, int ldb, int ldc,
       int zdiv, long long bz1, long long bz2, long long cz1,
       const int* __restrict__ seg_off, const int* __restrict__ tok,
       int Mfull, int epi,
       const float* __restrict__ bias, const float* __restrict__ resid) {
    extern __shared__ char smem[];
    uint32_t sb = smem_u32(smem);
    int tid = threadIdx.x, lane = tid & 31, warp = tid >> 5;
    int gid = lane >> 2, tig = lane & 3;
    int wm = warp & 1, wn = warp >> 1;

    int z  = blockIdx.z;
    int z1 = z / zdiv;
    int z2 = z - z1 * zdiv;
    const __half* Bb = Bw + z1 * bz1 + z2 * bz2;
    float*  Cb  = C;
    __half* Chb = Ch ? Ch + z1 * cz1 : (__half*)0;

    int Mseg = Mfull;
    const int* grows = nullptr;
    if (seg_off) {
        int s = seg_off[z2];
        Mseg  = seg_off[z2 + 1] - s;
        grows = tok + s;
        if (Chb) Chb += (long long)s * ldc;
        if (Cb)  Cb  += (long long)s * ldc;
    }
    int m0 = blockIdx.y * 128;
    if (m0 >= Mseg) return;
    int n0 = blockIdx.x * 128;

    float acc[4][4][4];
    #pragma unroll
    for (int i = 0; i < 4; i++)
        #pragma unroll
        for (int j = 0; j < 4; j++)
            #pragma unroll
            for (int u = 0; u < 4; u++) acc[i][j][u] = 0.0f;

    int nk = K / 64;

    auto issue = [&](int it) {
        int st = it % GH_STAGES;
        uint32_t abase = sb + st * GH_STAGE_BYTES;
        uint32_t bbase = abase + 16384;
        int k0 = it * 64;
        #pragma unroll
        for (int c = 0; c < 4; c++) {
            int ch = tid + 256 * c;
            int row = ch >> 3, kc = ch & 7;
            int gm = m0 + row;
            uint32_t dst = abase + SWZ((uint32_t)(row * 128 + kc * 16));
            const __half* src = A;
            int sz = 0;
            if (gm < Mseg) {
                long long rr = grows ? (long long)grows[gm] : (long long)gm;
                src = A + rr * (long long)lda + k0 + kc * 8;
                sz = 16;
            }
            cp_async16s(dst, src, sz);
        }
        #pragma unroll
        for (int c = 0; c < 4; c++) {
            int ch = tid + 256 * c;
            int row = ch >> 3, kc = ch & 7;
            uint32_t dst = bbase + SWZ((uint32_t)(row * 128 + kc * 16));
            cp_async16s(dst, Bb + (long long)(n0 + row) * ldb + k0 + kc * 8, 16);
        }
        cp_commit();
    };

    issue(0);
    if (nk > 1) issue(1);

    for (int it = 0; it < nk; it++) {
        if (it < nk - 1) cp_wait<1>(); else cp_wait<0>();
        __syncthreads();
        if (it + 2 < nk) issue(it + 2);

        int st = it % GH_STAGES;
        uint32_t abase = sb + st * GH_STAGE_BYTES;
        uint32_t bbase = abase + 16384;

        #pragma unroll
        for (int ks = 0; ks < 4; ks++) {
            uint32_t af[4][4];
            #pragma unroll
            for (int i = 0; i < 4; i++) {
                int row = wm * 64 + i * 16 + (lane & 15);
                uint32_t addr = abase +
                    SWZ((uint32_t)(row * 128 + ks * 32 + (lane >> 4) * 16));
                LDSM_X4(af[i][0], af[i][1], af[i][2], af[i][3], addr);
            }
            uint32_t bf[4][2];
            #pragma unroll
            for (int jp = 0; jp < 2; jp++) {
                int nrow = wn * 32 + jp * 16 + (lane & 15);
                uint32_t addr = bbase +
                    SWZ((uint32_t)(nrow * 128 + ks * 32 + (lane >> 4) * 16));
                uint32_t r0, r1, r2, r3;
                LDSM_X4(r0, r1, r2, r3, addr);
                bf[jp * 2][0] = r0; bf[jp * 2 + 1][0] = r1;
                bf[jp * 2][1] = r2; bf[jp * 2 + 1][1] = r3;
            }
            #pragma unroll
            for (int i = 0; i < 4; i++)
                #pragma unroll
                for (int j = 0; j < 4; j++)
                    mma_f16(acc[i][j], af[i][0], af[i][1], af[i][2], af[i][3],
                            bf[j][0], bf[j][1]);
        }
        __syncthreads();
    }

    #pragma unroll
    for (int i = 0; i < 4; i++)
        #pragma unroll
        for (int j = 0; j < 4; j++)
            #pragma unroll
            for (int h2 = 0; h2 < 2; h2++) {
                int r  = wm * 64 + i * 16 + gid + h2 * 8;
                int gm = m0 + r;
                if (gm >= Mseg) continue;
                int c  = wn * 32 + j * 8 + tig * 2;
                int gn = n0 + c;
                float v0 = acc[i][j][h2 * 2 + 0];
                float v1 = acc[i][j][h2 * 2 + 1];
                long long off = (long long)gm * ldc + gn;
                if (epi == 0) {
                    *reinterpret_cast<__half2*>(Chb + off) =
                        __floats2half2_rn(v0, v1);
                } else if (epi == 2) {
                    v0 = gelu_tanh(v0 + bias[gn]);
                    v1 = gelu_tanh(v1 + bias[gn + 1]);
                    *reinterpret_cast<__half2*>(Chb + off) =
                        __floats2half2_rn(v0, v1);
                } else {   // epi == 3
                    float2 rr = *reinterpret_cast<const float2*>(resid + off);
                    v0 = v0 + bias[gn] + rr.x;
                    v1 = v1 + bias[gn + 1] + rr.y;
                    *reinterpret_cast<float2*>(Cb + off) = make_float2(v0, v1);
                }
            }
}

// ================= fp16 flash attention =================
// grid (N/128, B*H), 256 thr. Warp w owns q rows [w*16, w*16+16).
// Half Q/K/V, double-buffered K/V, f32 softmax stats + accumulators.
// smem (halves): Qs[128][64] | Ks0 | Vs0 | Ks1 | Vs1 | Ps[8][16][136]
#define FAH_PS 136
#define FAH_KS(buf) (8192 + (buf)*16384)
#define FAH_VS(buf) (16384 + (buf)*16384)
#define FAH_P  40960
#define FAH_SMEM ((40960 + 8*16*FAH_PS)*2)   // 116736 B

__global__ void __launch_bounds__(256)
flash_attn_h() {
    extern __shared__ __half smh[];
    uint32_t sb = smem_u32(smh);

    int bh = blockIdx.y;
    int b = bh >> 4, h = bh & 15;
    int q0 = blockIdx.x * 128;
    int tid = threadIdx.x, lane = tid & 31, w = tid >> 5;
    int gid = lane >> 2, tig = lane & 3;

    const __half* Qg = g_q_h + ((long long)(b * N_ + q0)) * D_ + h * HD_;

    auto issue_kv = [&](int t) {
        int buf = t & 1;
        const __half* Kg = g_k_h + ((long long)(b * N_ + t * 128)) * D_ + h * HD_;
        const __half* Vg = g_v_h + ((long long)(b * N_ + t * 128)) * D_ + h * HD_;
        uint32_t kb = sb + FAH_KS(buf) * 2;
        uint32_t vb = sb + FAH_VS(buf) * 2;
        #pragma unroll
        for (int p = 0; p < 4; p++) {
            int ch = tid + 256 * p;             // 1024 chunks each
            int r = ch >> 3, c16 = ch & 7;
            uint32_t doff = SWZ((uint32_t)(r * 128 + c16 * 16));
            cp_async16s(kb + doff, Kg + (long long)r * D_ + c16 * 8, 16);
            cp_async16s(vb + doff, Vg + (long long)r * D_ + c16 * 8, 16);
        }
        cp_commit();
    };

    // initial: Q + tile 0
    {
        uint32_t qb = sb;
        #pragma unroll
        for (int p = 0; p < 4; p++) {
            int ch = tid + 256 * p;
            int r = ch >> 3, c16 = ch & 7;
            uint32_t doff = SWZ((uint32_t)(r * 128 + c16 * 16));
            cp_async16s(qb + doff, Qg + (long long)r * D_ + c16 * 8, 16);
        }
        cp_commit();
        issue_kv(0);
    }

    // Q fragments (constant across tiles)
    uint32_t qf[4][4];
    cp_wait<1>();          // Q group done (kv0 may still be in flight)
    __syncthreads();
    #pragma unroll
    for (int ks = 0; ks < 4; ks++) {
        int row = w * 16 + (lane & 15);
        uint32_t addr = sb + SWZ((uint32_t)(row * 128 + ks * 32 + (lane >> 4) * 16));
        LDSM_X4(qf[ks][0], qf[ks][1], qf[ks][2], qf[ks][3], addr);
    }

    float of[8][4];
    #pragma unroll
    for (int j = 0; j < 8; j++)
        #pragma unroll
        for (int u = 0; u < 4; u++) of[j][u] = 0.0f;
    float M0 = -1e30f, M1 = -1e30f, L0 = 0.f, L1 = 0.f;
    const float CE = 0.125f * 1.4426950408889634f;

    __half* Pw = smh + FAH_P + w * 16 * FAH_PS;
    uint32_t pwb = sb + (FAH_P + w * 16 * FAH_PS) * 2;

    for (int t = 0; t < 8; t++) {
        __syncthreads();                       // everyone done with buf t^1
        if (t < 7) issue_kv(t + 1);
        if (t < 7) cp_wait<1>(); else cp_wait<0>();
        __syncthreads();                       // tile t visible

        int buf = t & 1;
        uint32_t kb = sb + FAH_KS(buf) * 2;
        uint32_t vb = sb + FAH_VS(buf) * 2;

        // S = Q @ K^T
        float sf[16][4];
        #pragma unroll
        for (int j = 0; j < 16; j++)
            #pragma unroll
            for (int u = 0; u < 4; u++) sf[j][u] = 0.0f;
        #pragma unroll
        for (int ks = 0; ks < 4; ks++) {
            #pragma unroll
            for (int jj = 0; jj < 8; jj++) {
                int nrow = jj * 16 + (lane & 15);
                uint32_t addr = kb +
                    SWZ((uint32_t)(nrow * 128 + ks * 32 + (lane >> 4) * 16));
                uint32_t r0, r1, r2, r3;
                LDSM_X4(r0, r1, r2, r3, addr);
                mma_f16(sf[jj * 2],     qf[ks][0], qf[ks][1], qf[ks][2], qf[ks][3], r0, r2);
                mma_f16(sf[jj * 2 + 1], qf[ks][0], qf[ks][1], qf[ks][2], qf[ks][3], r1, r3);
            }
        }

        // online softmax
        float mx0 = -1e30f, mx1 = -1e30f;
        #pragma unroll
        for (int j = 0; j < 16; j++) {
            mx0 = fmaxf(mx0, fmaxf(sf[j][0], sf[j][1]));
            mx1 = fmaxf(mx1, fmaxf(sf[j][2], sf[j][3]));
        }
        mx0 = fmaxf(mx0, __shfl_xor_sync(0xffffffffu, mx0, 1));
        mx0 = fmaxf(mx0, __shfl_xor_sync(0xffffffffu, mx0, 2));
        mx1 = fmaxf(mx1, __shfl_xor_sync(0xffffffffu, mx1, 1));
        mx1 = fmaxf(mx1, __shfl_xor_sync(0xffffffffu, mx1, 2));
        float nM0 = fmaxf(M0, mx0), nM1 = fmaxf(M1, mx1);
        float corr0 = fast_exp2(CE * (M0 - nM0));
        float corr1 = fast_exp2(CE * (M1 - nM1));

        float s0 = 0.f, s1 = 0.f;
        #pragma unroll
        for (int j = 0; j < 16; j++) {
            float p0 = fast_exp2(CE * (sf[j][0] - nM0));
            float p1 = fast_exp2(CE * (sf[j][1] - nM0));
            float p2 = fast_exp2(CE * (sf[j][2] - nM1));
            float p3 = fast_exp2(CE * (sf[j][3] - nM1));
            s0 += p0 + p1; s1 += p2 + p3;
            *reinterpret_cast<__half2*>(Pw + gid * FAH_PS + j * 8 + tig * 2) =
                __floats2half2_rn(p0, p1);
            *reinterpret_cast<__half2*>(Pw + (gid + 8) * FAH_PS + j * 8 + tig * 2) =
                __floats2half2_rn(p2, p3);
        }
        s0 += __shfl_xor_sync(0xffffffffu, s0, 1);
        s0 += __shfl_xor_sync(0xffffffffu, s0, 2);
        s1 += __shfl_xor_sync(0xffffffffu, s1, 1);
        s1 += __shfl_xor_sync(0xffffffffu, s1, 2);
        L0 = L0 * corr0 + s0;
        L1 = L1 * corr1 + s1;
        M0 = nM0; M1 = nM1;

        #pragma unroll
        for (int j = 0; j < 8; j++) {
            of[j][0] *= corr0; of[j][1] *= corr0;
            of[j][2] *= corr1; of[j][3] *= corr1;
        }
        __syncwarp();

        // O += P @ V   (A = P[16,128] from Pw, B = V^T via ldmatrix.trans)
        #pragma unroll
        for (int k2 = 0; k2 < 8; k2++) {
            uint32_t a0, a1, a2, a3;
            uint32_t aaddr = pwb + (uint32_t)((lane & 15) * FAH_PS * 2 +
                                              k2 * 32 + (lane >> 4) * 16);
            LDSM_X4(a0, a1, a2, a3, aaddr);
            #pragma unroll
            for (int jp = 0; jp < 4; jp++) {
                int vrow = k2 * 16 + (lane & 15);
                uint32_t vaddr = vb +
                    SWZ((uint32_t)(vrow * 128 + jp * 32 + (lane >> 4) * 16));
                uint32_t r0, r1, r2, r3;
                LDSM_X4_T(r0, r1, r2, r3, vaddr);
                mma_f16(of[jp * 2],     a0, a1, a2, a3, r0, r1);
                mma_f16(of[jp * 2 + 1], a0, a1, a2, a3, r2, r3);
            }
        }
    }

    float i0 = 1.0f / L0, i1 = 1.0f / L1;
    __half* Og = g_att_h + ((long long)(b * N_ + q0 + w * 16)) * D_ + h * HD_;
    #pragma unroll
    for (int j = 0; j < 8; j++) {
        *reinterpret_cast<__half2*>(&Og[(long long)gid * D_ + j * 8 + tig * 2]) =
            __floats2half2_rn(of[j][0] * i0, of[j][1] * i0);
        *reinterpret_cast<__half2*>(&Og[(long long)(gid + 8) * D_ + j * 8 + tig * 2]) =
            __floats2half2_rn(of[j][2] * i1, of[j][3] * i1);
    }
}

// ---------------- small kernels ----------------
// 8 floats -> 8 halves per thread, one 16B store
__global__ void f2h_kernel(const float* __restrict__ src, __half* __restrict__ dst,
                           int n8) {
    int i = blockIdx.x * blockDim.x + threadIdx.x;
    if (i >= n8) return;
    const float4* s4 = reinterpret_cast<const float4*>(src);
    float4 a = s4[i * 2], b = s4[i * 2 + 1];
    union { __half2 h[4]; uint4 u; } pack;
    pack.h[0] = __floats2half2_rn(a.x, a.y);
    pack.h[1] = __floats2half2_rn(a.z, a.w);
    pack.h[2] = __floats2half2_rn(b.x, b.y);
    pack.h[3] = __floats2half2_rn(b.z, b.w);
    reinterpret_cast<uint4*>(dst)[i] = pack.u;
}

__global__ void ln_kernel(const float* __restrict__ x, const float* __restrict__ add,
                          const float* __restrict__ g, const float* __restrict__ b,
                          float* __restrict__ out, __half* __restrict__ out_h,
                          float* __restrict__ hout, int do_init) {
    __shared__ float sh[33];
    long long row = blockIdx.x;
    int tid = threadIdx.x;
    if (do_init && blockIdx.x == 0 && tid < E_) g_cnt[tid] = 0;
    float v[4];
    #pragma unroll
    for (int i = 0; i < 4; i++) {
        int c = tid + 256 * i;
        v[i] = x[row * D_ + c];
        if (add)  v[i] += add[row * D_ + c];
        if (hout) hout[row * D_ + c] = v[i];
    }
    float s = block_reduce_sum(v[0] + v[1] + v[2] + v[3], sh);
    float m = s * (1.0f / D_);
    float q = 0.f;
    #pragma unroll
    for (int i = 0; i < 4; i++) { float d = v[i] - m; q += d * d; }
    q = block_reduce_sum(q, sh);
    float rstd = rsqrtf(q * (1.0f / D_) + 1e-5f);
    #pragma unroll
    for (int i = 0; i < 4; i++) {
        int c = tid + 256 * i;
        float r = (v[i] - m) * rstd * g[c] + b[c];
        if (out)   out[row * D_ + c] = r;
        if (out_h) out_h[row * D_ + c] = __float2half(r);
    }
}

__global__ void router_kernel(const float* __restrict__ Wr) {
    int warp = (blockIdx.x * blockDim.x + threadIdx.x) >> 5;
    int lane = threadIdx.x & 31;
    if (warp >= T_) return;
    const float* xr = g_xn + (long long)warp * D_;
    float acc[E_];
    #pragma unroll
    for (int e = 0; e < E_; e++) acc[e] = 0.f;
    for (int i = lane; i < D_; i += 32) {
        float xv = xr[i];
        #pragma unroll
        for (int e = 0; e < E_; e++) acc[e] += xv * Wr[e * D_ + i];
    }
    #pragma unroll
    for (int e = 0; e < E_; e++)
        #pragma unroll
        for (int o = 16; o; o >>= 1) acc[e] += __shfl_xor_sync(0xffffffffu, acc[e], o);
    if (lane == 0) {
        float mx = acc[0];
        #pragma unroll
        for (int e = 1; e < E_; e++) mx = fmaxf(mx, acc[e]);
        float p[E_], s = 0.f;
        #pragma unroll
        for (int e = 0; e < E_; e++) { p[e] = expf(acc[e] - mx); s += p[e]; }
        float inv = 1.0f / s;
        #pragma unroll
        for (int e = 0; e < E_; e++) { p[e] *= inv; g_probs[warp * E_ + e] = p[e]; }
        int i0 = 0;
        #pragma unroll
        for (int e = 1; e < E_; e++) if (p[e] > p[i0]) i0 = e;
        int i1 = (i0 == 0) ? 1 : 0;
        #pragma unroll
        for (int e = 0; e < E_; e++) if (e != i0 && p[e] > p[i1]) i1 = e;
        float v0 = p[i0], v1 = p[i1];
        float wsum = v0 + v1 + 1e-6f;
        g_topi[warp * 2 + 0] = i0;
        g_topi[warp * 2 + 1] = i1;
        g_topw[warp * 2 + 0] = v0 / wsum;
        g_topw[warp * 2 + 1] = v1 / wsum;
        atomicAdd(&g_cnt[i0], 1);
        atomicAdd(&g_cnt[i1], 1);
    }
}

__global__ void scan_scatter_kernel() {
    int tid = threadIdx.x;
    if (tid == 0) {
        int s = 0;
        for (int e = 0; e < E_; e++) { g_off[e] = s; s += g_cnt[e]; g_ctr[e] = 0; }
        g_off[E_] = s;
    }
    __syncthreads();
    for (int idx = tid; idx < A_; idx += 256) {
        int e = g_topi[idx];
        int pos = g_off[e] + atomicAdd(&g_ctr[e], 1);
        g_tok[pos]  = idx >> 1;
        g_aidx[idx] = pos;
    }
}

// combine Q,K,V (half proj -> half q/k/v)
__global__ void combine_qkv_kernel() {
    long long t = blockIdx.x;
    int tid = threadIdx.x;
    int a0 = g_aidx[t * 2 + 0], a1 = g_aidx[t * 2 + 1];
    float w0 = g_topw[t * 2 + 0], w1 = g_topw[t * 2 + 1];
    const __half2* pQ = reinterpret_cast<const __half2*>(g_projQKV);
    const __half2* pK = reinterpret_cast<const __half2*>(g_projQKV + (long long)A_ * D_);
    const __half2* pV = reinterpret_cast<const __half2*>(g_projQKV + 2LL * A_ * D_);
    long long r0 = (long long)a0 * (D_ / 2), r1 = (long long)a1 * (D_ / 2);
    long long tb = t * (D_ / 2);
    #pragma unroll
    for (int i = 0; i < 2; i++) {
        int c = tid + 256 * i;
        float2 q0 = __half22float2(pQ[r0 + c]), q1 = __half22float2(pQ[r1 + c]);
        float2 k0 = __half22float2(pK[r0 + c]), k1 = __half22float2(pK[r1 + c]);
        float2 v0 = __half22float2(pV[r0 + c]), v1 = __half22float2(pV[r1 + c]);
        reinterpret_cast<__half2*>(g_q_h)[tb + c] =
            __floats2half2_rn(w0 * q0.x + w1 * q1.x, w0 * q0.y + w1 * q1.y);
        reinterpret_cast<__half2*>(g_k_h)[tb + c] =
            __floats2half2_rn(w0 * k0.x + w1 * k1.x, w0 * k0.y + w1 * k1.y);
        reinterpret_cast<__half2*>(g_v_h)[tb + c] =
            __floats2half2_rn(w0 * v0.x + w1 * v1.x, w0 * v0.y + w1 * v1.y);
    }
}

// combine O (half proj slot 0 -> f32 g_o)
__global__ void combine_o_kernel() {
    long long t = blockIdx.x;
    int tid = threadIdx.x;
    int a0 = g_aidx[t * 2 + 0], a1 = g_aidx[t * 2 + 1];
    float w0 = g_topw[t * 2 + 0], w1 = g_topw[t * 2 + 1];
    const __half2* pO = reinterpret_cast<const __half2*>(g_projQKV);
    long long r0 = (long long)a0 * (D_ / 2), r1 = (long long)a1 * (D_ / 2);
    long long tb = t * (D_ / 2);
    #pragma unroll
    for (int i = 0; i < 2; i++) {
        int c = tid + 256 * i;
        float2 o0 = __half22float2(pO[r0 + c]), o1 = __half22float2(pO[r1 + c]);
        reinterpret_cast<float2*>(g_o)[tb + c] =
            make_float2(w0 * o0.x + w1 * o1.x, w0 * o0.y + w1 * o1.y);
    }
}

__global__ void lb_kernel(float* __restrict__ out, int out_size) {
    __shared__ float sh[256];
    int tid = threadIdx.x;
    float pl[E_];
    #pragma unroll
    for (int e = 0; e < E_; e++) pl[e] = 0.f;
    for (int t = tid; t < T_; t += 256)
        #pragma unroll
        for (int e = 0; e < E_; e++) pl[e] += g_probs[t * E_ + e];
    float pe[E_];
    for (int e = 0; e < E_; e++) {
        sh[tid] = pl[e];
        __syncthreads();
        for (int o = 128; o; o >>= 1) {
            if (tid < o) sh[tid] += sh[tid + o];
            __syncthreads();
        }
        pe[e] = sh[0];
        __syncthreads();
    }
    if (tid == 0) {
        float lb = 0.f;
        float denom = (float)A_ + 1e-6f;
        for (int e = 0; e < E_; e++)
            lb += ((float)g_cnt[e] / denom) * pe[e];
        lb *= (float)E_;
        if (out_size > (int)TD) out[TD] = lb;
    }
}

// ---------------- host launch ----------------
extern "C" void kernel_launch(void* const* d_in, const int* in_sizes, int n_in,
                              void* d_out, int out_size) {
    const float* x   = (const float*)d_in[0];
    const float* Wr  = (const float*)d_in[1];
    const float* Wq  = (const float*)d_in[2];
    const float* Wk  = (const float*)d_in[3];
    const float* Wv  = (const float*)d_in[4];
    const float* Wo  = (const float*)d_in[5];
    const float* W1  = (const float*)d_in[6];
    const float* b1  = (const float*)d_in[7];
    const float* W2  = (const float*)d_in[8];
    const float* b2  = (const float*)d_in[9];
    const float* g1  = (const float*)d_in[10];
    const float* be1 = (const float*)d_in[11];
    const float* g2  = (const float*)d_in[12];
    const float* be2 = (const float*)d_in[13];
    float* out = (float*)d_out;

    float  *p_xn, *p_h, *p_o;
    __half *p_xn_h, *p_att_h, *p_hn_h, *p_ff1_h, *p_projQKV;
    __half *p_Wqkv_h, *p_Wo_h, *p_W1_h, *p_W2_h;
    int *p_off, *p_tok;
    cudaGetSymbolAddress((void**)&p_xn,     g_xn);
    cudaGetSymbolAddress((void**)&p_xn_h,   g_xn_h);
    cudaGetSymbolAddress((void**)&p_projQKV,g_projQKV);
    cudaGetSymbolAddress((void**)&p_att_h,  g_att_h);
    cudaGetSymbolAddress((void**)&p_o,      g_o);
    cudaGetSymbolAddress((void**)&p_h,      g_h);
    cudaGetSymbolAddress((void**)&p_hn_h,   g_hn_h);
    cudaGetSymbolAddress((void**)&p_ff1_h,  g_ff1_h);
    cudaGetSymbolAddress((void**)&p_Wqkv_h, g_Wqkv_h);
    cudaGetSymbolAddress((void**)&p_Wo_h,   g_Wo_h);
    cudaGetSymbolAddress((void**)&p_W1_h,   g_W1_h);
    cudaGetSymbolAddress((void**)&p_W2_h,   g_W2_h);
    cudaGetSymbolAddress((void**)&p_off,    g_off);
    cudaGetSymbolAddress((void**)&p_tok,    g_tok);

    const long long EDD = (long long)E_ * D_ * D_;
    const long long DD  = (long long)D_ * D_;
    cudaFuncSetAttribute(gemm_h,
                         cudaFuncAttributeMaxDynamicSharedMemorySize, GH_SMEM);
    cudaFuncSetAttribute(flash_attn_h,
                         cudaFuncAttributeMaxDynamicSharedMemorySize, FAH_SMEM);

    // weight conversions
    {
        int n8 = (int)(EDD / 8);
        int blk = (n8 + 255) / 256;
        f2h_kernel<<<blk, 256>>>(Wq, p_Wqkv_h, n8);
        f2h_kernel<<<blk, 256>>>(Wk, p_Wqkv_h + EDD, n8);
        f2h_kernel<<<blk, 256>>>(Wv, p_Wqkv_h + 2 * EDD, n8);
        f2h_kernel<<<blk, 256>>>(Wo, p_Wo_h, n8);
        int nf = (int)((long long)FF_ * D_ * D_ / 8);
        int blkf = (nf + 255) / 256;
        f2h_kernel<<<blkf, 256>>>(W1, p_W1_h, nf);
        f2h_kernel<<<blkf, 256>>>(W2, p_W2_h, nf);
    }

    ln_kernel<<<T_, 256>>>(x, nullptr, g1, be1, p_xn, p_xn_h, nullptr, 1);
    router_kernel<<<T_ / 8, 256>>>(Wr);
    scan_scatter_kernel<<<1, 256>>>();

    // merged grouped QKV GEMM: z = p*E + e
    gemm_h<<<dim3(D_ / 128, A_ / 128, 3 * E_), 256, GH_SMEM>>>(
        p_xn_h, p_Wqkv_h, nullptr, p_projQKV,
        D_, D_, D_, D_, E_, EDD, DD, (long long)A_ * D_,
        p_off, p_tok, A_, 0, nullptr, nullptr);
    combine_qkv_kernel<<<T_, 256>>>();

    // fp16 flash attention
    flash_attn_h<<<dim3(N_ / 128, B_ * H_), 256, FAH_SMEM>>>();

    // grouped O projection (into proj slot 0) + combine
    gemm_h<<<dim3(D_ / 128, A_ / 128, E_), 256, GH_SMEM>>>(
        p_att_h, p_Wo_h, nullptr, p_projQKV,
        D_, D_, D_, D_, E_, 0, DD, 0,
        p_off, p_tok, A_, 0, nullptr, nullptr);
    combine_o_kernel<<<T_, 256>>>();

    // h = x + o ; hn = LN2(h) -> half
    ln_kernel<<<T_, 256>>>(x, p_o, g2, be2, nullptr, p_hn_h, p_h, 0);

    // FFN1
    gemm_h<<<dim3(FF_ * D_ / 128, T_ / 128, 1), 256, GH_SMEM>>>(
        p_hn_h, p_W1_h, nullptr, p_ff1_h,
        D_, D_, D_, FF_ * D_, 1, 0, 0, 0,
        nullptr, nullptr, T_, 2, b1, nullptr);

    // FFN2 -> d_out
    gemm_h<<<dim3(D_ / 128, T_ / 128, 1), 256, GH_SMEM>>>(
        p_ff1_h, p_W2_h, out, nullptr,
        FF_ * D_, FF_ * D_, FF_ * D_, D_, 1, 0, 0, 0,
        nullptr, nullptr, T_, 3, b2, p_h);

    lb_kernel<<<1, 256>>>(out, out_size);
}

// round 7
// speedup vs baseline: 2.6367x; 1.0180x over previous
#include <cuda_runtime.h>
#include <cuda_fp16.h>
#include <math.h>
#include <stdint.h>

// ---------------- problem constants ----------------
#define B_   4
#define N_   1024
#define D_   1024
#define H_   16
#define E_   12
#define KTOP 2
#define FF_  4
#define HD_  64
#define T_   (B_*N_)
#define A_   (T_*KTOP)
#define TD   ((long long)T_*D_)

// ---------------- static device scratch ----------------
__device__ float  g_xn   [T_*D_];
__device__ __half g_xn_h [T_*D_];
__device__ float  g_probs[T_*E_];
__device__ int    g_topi [T_*KTOP];
__device__ float  g_topw [T_*KTOP];
__device__ int    g_cnt  [E_];
__device__ int    g_off  [E_+1];
__device__ int    g_ctr  [E_];
__device__ int    g_tok  [A_];
__device__ int    g_aidx [T_*KTOP];
__device__ __half g_projQKV[3LL*A_*D_];   // Q | K | V slots; O reuses slot 0
__device__ __half g_q_h  [T_*D_];
__device__ __half g_k_h  [T_*D_];
__device__ __half g_v_h  [T_*D_];
__device__ __half g_att_h[T_*D_];
__device__ float  g_h    [T_*D_];
__device__ __half g_hn_h [T_*D_];
__device__ __half g_ff1_h[T_*FF_*D_];
// half weight shadows
__device__ __half g_Wqkv_h[3LL*E_*D_*D_];
__device__ __half g_Wo_h  [(long long)E_*D_*D_];
__device__ __half g_W1_h  [(long long)FF_*D_*D_];
__device__ __half g_W2_h  [(long long)FF_*D_*D_];

// ---------------- PTX helpers ----------------
__device__ __forceinline__ uint32_t smem_u32(const void* p) {
    uint32_t a;
    asm("{ .reg .u64 t; cvta.to.shared.u64 t, %1; cvt.u32.u64 %0, t; }"
        : "=r"(a) : "l"(p));
    return a;
}
__device__ __forceinline__ void cp_async16s(uint32_t s, const void* g, int sz) {
    asm volatile("cp.async.cg.shared.global [%0], [%1], 16, %2;\n"
                 :: "r"(s), "l"(g), "r"(sz));
}
__device__ __forceinline__ void cp_commit() {
    asm volatile("cp.async.commit_group;\n");
}
template<int NN>
__device__ __forceinline__ void cp_wait() {
    asm volatile("cp.async.wait_group %0;\n" :: "n"(NN));
}
#define SWZ(o) ((o) ^ (((o) >> 3) & 0x70))

#define LDSM_X4(r0, r1, r2, r3, addr) \
    asm volatile("ldmatrix.sync.aligned.m8n8.x4.shared.b16 {%0,%1,%2,%3}, [%4];" \
        : "=r"(r0), "=r"(r1), "=r"(r2), "=r"(r3) : "r"(addr))
#define LDSM_X4_T(r0, r1, r2, r3, addr) \
    asm volatile("ldmatrix.sync.aligned.m8n8.x4.trans.shared.b16 {%0,%1,%2,%3}, [%4];" \
        : "=r"(r0), "=r"(r1), "=r"(r2), "=r"(r3) : "r"(addr))

__device__ __forceinline__ void mma_f16(float c[4],
        uint32_t a0, uint32_t a1, uint32_t a2, uint32_t a3,
        uint32_t b0, uint32_t b1) {
    asm volatile(
        "mma.sync.aligned.m16n8k16.row.col.f32.f16.f16.f32 "
        "{%0,%1,%2,%3}, {%4,%5,%6,%7}, {%8,%9}, {%0,%1,%2,%3};"
        : "+f"(c[0]), "+f"(c[1]), "+f"(c[2]), "+f"(c[3])
        : "r"(a0), "r"(a1), "r"(a2), "r"(a3), "r"(b0), "r"(b1));
}
__device__ __forceinline__ float fast_exp2(float x) {
    float y;
    asm("ex2.approx.f32 %0, %1;" : "=f"(y) : "f"(x));
    return y;
}
__device__ __forceinline__ uint32_t pack_h2(float a, float b) {
    __half2 h = __floats2half2_rn(a, b);
    uint32_t u;
    asm("mov.b32 %0, %1;" : "=r"(u) : "r"(*reinterpret_cast<uint32_t*>(&h)));
    return u;
}
__device__ __forceinline__ float gelu_tanh(float x) {
    float x3 = x * x * x;
    return 0.5f * x * (1.0f + tanhf(0.7978845608028654f * (x + 0.044715f * x3)));
}
__device__ __forceinline__ float block_reduce_sum(float v, float* sh) {
    int tid = threadIdx.x;
    #pragma unroll
    for (int o = 16; o; o >>= 1) v += __shfl_xor_sync(0xffffffffu, v, o);
    if ((tid & 31) == 0) sh[tid >> 5] = v;
    __syncthreads();
    if (tid < 32) {
        v = (tid < (int)(blockDim.x >> 5)) ? sh[tid] : 0.0f;
        #pragma unroll
        for (int o = 16; o; o >>= 1) v += __shfl_xor_sync(0xffffffffu, v, o);
        if (tid == 0) sh[0] = v;
    }
    __syncthreads();
    float r = sh[0];
    __syncthreads();
    return r;
}

// ================= fp16 HMMA GEMM (2 CTAs/SM) =================
#define GH_STAGES 3
#define GH_STAGE_BYTES 32768
#define GH_SMEM (GH_STAGES*GH_STAGE_BYTES)

__global__ void __launch_bounds__(256, 2)
gemm_h(const __half* __restrict__ A, const __half* __restrict__ Bw,
       float* __restrict__ C, __half* __restrict__ Ch,
       int K, int lda, int ldb, int ldc,
       int zdiv, long long bz1, long long bz2, long long cz1,
       const int* __restrict__ seg_off, const int* __restrict__ tok,
       int Mfull, int epi,
       const float* __restrict__ bias, const float* __restrict__ resid) {
    extern __shared__ char smem[];
    uint32_t sb = smem_u32(smem);
    int tid = threadIdx.x, lane = tid & 31, warp = tid >> 5;
    int gid = lane >> 2, tig = lane & 3;
    int wm = warp & 1, wn = warp >> 1;

    int z  = blockIdx.z;
    int z1 = z / zdiv;
    int z2 = z - z1 * zdiv;
    const __half* Bb = Bw + z1 * bz1 + z2 * bz2;
    float*  Cb  = C;
    __half* Chb = Ch ? Ch + z1 * cz1 : (__half*)0;

    int Mseg = Mfull;
    const int* grows = nullptr;
    if (seg_off) {
        int s = seg_off[z2];
        Mseg  = seg_off[z2 + 1] - s;
        grows = tok + s;
        if (Chb) Chb += (long long)s * ldc;
        if (Cb)  Cb  += (long long)s * ldc;
    }
    int m0 = blockIdx.y * 128;
    if (m0 >= Mseg) return;
    int n0 = blockIdx.x * 128;

    float acc[4][4][4];
    #pragma unroll
    for (int i = 0; i < 4; i++)
        #pragma unroll
        for (int j = 0; j < 4; j++)
            #pragma unroll
            for (int u = 0; u < 4; u++) acc[i][j][u] = 0.0f;

    int nk = K / 64;

    auto issue = [&](int it) {
        int st = it % GH_STAGES;
        uint32_t abase = sb + st * GH_STAGE_BYTES;
        uint32_t bbase = abase + 16384;
        int k0 = it * 64;
        #pragma unroll
        for (int c = 0; c < 4; c++) {
            int ch = tid + 256 * c;
            int row = ch >> 3, kc = ch & 7;
            int gm = m0 + row;
            uint32_t dst = abase + SWZ((uint32_t)(row * 128 + kc * 16));
            const __half* src = A;
            int sz = 0;
            if (gm < Mseg) {
                long long rr = grows ? (long long)grows[gm] : (long long)gm;
                src = A + rr * (long long)lda + k0 + kc * 8;
                sz = 16;
            }
            cp_async16s(dst, src, sz);
        }
        #pragma unroll
        for (int c = 0; c < 4; c++) {
            int ch = tid + 256 * c;
            int row = ch >> 3, kc = ch & 7;
            uint32_t dst = bbase + SWZ((uint32_t)(row * 128 + kc * 16));
            cp_async16s(dst, Bb + (long long)(n0 + row) * ldb + k0 + kc * 8, 16);
        }
        cp_commit();
    };

    issue(0);
    if (nk > 1) issue(1);

    for (int it = 0; it < nk; it++) {
        if (it < nk - 1) cp_wait<1>(); else cp_wait<0>();
        __syncthreads();
        if (it + 2 < nk) issue(it + 2);

        int st = it % GH_STAGES;
        uint32_t abase = sb + st * GH_STAGE_BYTES;
        uint32_t bbase = abase + 16384;

        #pragma unroll
        for (int ks = 0; ks < 4; ks++) {
            uint32_t af[4][4];
            #pragma unroll
            for (int i = 0; i < 4; i++) {
                int row = wm * 64 + i * 16 + (lane & 15);
                uint32_t addr = abase +
                    SWZ((uint32_t)(row * 128 + ks * 32 + (lane >> 4) * 16));
                LDSM_X4(af[i][0], af[i][1], af[i][2], af[i][3], addr);
            }
            uint32_t bf[4][2];
            #pragma unroll
            for (int jp = 0; jp < 2; jp++) {
                int nrow = wn * 32 + jp * 16 + (lane & 15);
                uint32_t addr = bbase +
                    SWZ((uint32_t)(nrow * 128 + ks * 32 + (lane >> 4) * 16));
                uint32_t r0, r1, r2, r3;
                LDSM_X4(r0, r1, r2, r3, addr);
                bf[jp * 2][0] = r0; bf[jp * 2 + 1][0] = r1;
                bf[jp * 2][1] = r2; bf[jp * 2 + 1][1] = r3;
            }
            #pragma unroll
            for (int i = 0; i < 4; i++)
                #pragma unroll
                for (int j = 0; j < 4; j++)
                    mma_f16(acc[i][j], af[i][0], af[i][1], af[i][2], af[i][3],
                            bf[j][0], bf[j][1]);
        }
        __syncthreads();
    }

    #pragma unroll
    for (int i = 0; i < 4; i++)
        #pragma unroll
        for (int j = 0; j < 4; j++)
            #pragma unroll
            for (int h2 = 0; h2 < 2; h2++) {
                int r  = wm * 64 + i * 16 + gid + h2 * 8;
                int gm = m0 + r;
                if (gm >= Mseg) continue;
                int c  = wn * 32 + j * 8 + tig * 2;
                int gn = n0 + c;
                float v0 = acc[i][j][h2 * 2 + 0];
                float v1 = acc[i][j][h2 * 2 + 1];
                long long off = (long long)gm * ldc + gn;
                if (epi == 0) {
                    *reinterpret_cast<__half2*>(Chb + off) =
                        __floats2half2_rn(v0, v1);
                } else if (epi == 2) {
                    v0 = gelu_tanh(v0 + bias[gn]);
                    v1 = gelu_tanh(v1 + bias[gn + 1]);
                    *reinterpret_cast<__half2*>(Chb + off) =
                        __floats2half2_rn(v0, v1);
                } else {   // epi == 3
                    float2 rr = *reinterpret_cast<const float2*>(resid + off);
                    v0 = v0 + bias[gn] + rr.x;
                    v1 = v1 + bias[gn + 1] + rr.y;
                    *reinterpret_cast<float2*>(Cb + off) = make_float2(v0, v1);
                }
            }
}

// ================= fp16 flash attention (FA2 register P-reuse) =================
// smem (halves): Qs[0,8192) | K0[8192,16384) | V0[16384,24576) | K1 | V1
#define FAH_KS(buf) (8192 + (buf)*16384)
#define FAH_VS(buf) (16384 + (buf)*16384)
#define FAH_SMEM (40960*2)   // 81920 B

__global__ void __launch_bounds__(256)
flash_attn_h() {
    extern __shared__ __half smh[];
    uint32_t sb = smem_u32(smh);

    int bh = blockIdx.y;
    int b = bh >> 4, h = bh & 15;
    int q0 = blockIdx.x * 128;
    int tid = threadIdx.x, lane = tid & 31, w = tid >> 5;
    int gid = lane >> 2, tig = lane & 3;

    const __half* Qg = g_q_h + ((long long)(b * N_ + q0)) * D_ + h * HD_;

    auto issue_kv = [&](int t) {
        int buf = t & 1;
        const __half* Kg = g_k_h + ((long long)(b * N_ + t * 128)) * D_ + h * HD_;
        const __half* Vg = g_v_h + ((long long)(b * N_ + t * 128)) * D_ + h * HD_;
        uint32_t kb = sb + FAH_KS(buf) * 2;
        uint32_t vb = sb + FAH_VS(buf) * 2;
        #pragma unroll
        for (int p = 0; p < 4; p++) {
            int ch = tid + 256 * p;
            int r = ch >> 3, c16 = ch & 7;
            uint32_t doff = SWZ((uint32_t)(r * 128 + c16 * 16));
            cp_async16s(kb + doff, Kg + (long long)r * D_ + c16 * 8, 16);
            cp_async16s(vb + doff, Vg + (long long)r * D_ + c16 * 8, 16);
        }
        cp_commit();
    };

    {
        uint32_t qb = sb;
        #pragma unroll
        for (int p = 0; p < 4; p++) {
            int ch = tid + 256 * p;
            int r = ch >> 3, c16 = ch & 7;
            uint32_t doff = SWZ((uint32_t)(r * 128 + c16 * 16));
            cp_async16s(qb + doff, Qg + (long long)r * D_ + c16 * 8, 16);
        }
        cp_commit();
        issue_kv(0);
    }

    uint32_t qf[4][4];
    cp_wait<1>();
    __syncthreads();
    #pragma unroll
    for (int ks = 0; ks < 4; ks++) {
        int row = w * 16 + (lane & 15);
        uint32_t addr = sb + SWZ((uint32_t)(row * 128 + ks * 32 + (lane >> 4) * 16));
        LDSM_X4(qf[ks][0], qf[ks][1], qf[ks][2], qf[ks][3], addr);
    }

    float of[8][4];
    #pragma unroll
    for (int j = 0; j < 8; j++)
        #pragma unroll
        for (int u = 0; u < 4; u++) of[j][u] = 0.0f;
    float M0 = -1e30f, M1 = -1e30f, L0 = 0.f, L1 = 0.f;
    const float CE = 0.125f * 1.4426950408889634f;

    for (int t = 0; t < 8; t++) {
        __syncthreads();
        if (t < 7) issue_kv(t + 1);
        if (t < 7) cp_wait<1>(); else cp_wait<0>();
        __syncthreads();

        int buf = t & 1;
        uint32_t kb = sb + FAH_KS(buf) * 2;
        uint32_t vb = sb + FAH_VS(buf) * 2;

        // S = Q @ K^T
        float sf[16][4];
        #pragma unroll
        for (int j = 0; j < 16; j++)
            #pragma unroll
            for (int u = 0; u < 4; u++) sf[j][u] = 0.0f;
        #pragma unroll
        for (int ks = 0; ks < 4; ks++) {
            #pragma unroll
            for (int jj = 0; jj < 8; jj++) {
                int nrow = jj * 16 + (lane & 15);
                uint32_t addr = kb +
                    SWZ((uint32_t)(nrow * 128 + ks * 32 + (lane >> 4) * 16));
                uint32_t r0, r1, r2, r3;
                LDSM_X4(r0, r1, r2, r3, addr);
                mma_f16(sf[jj * 2],     qf[ks][0], qf[ks][1], qf[ks][2], qf[ks][3], r0, r2);
                mma_f16(sf[jj * 2 + 1], qf[ks][0], qf[ks][1], qf[ks][2], qf[ks][3], r1, r3);
            }
        }

        // online softmax (rows gid -> M0/L0, gid+8 -> M1/L1)
        float mx0 = -1e30f, mx1 = -1e30f;
        #pragma unroll
        for (int j = 0; j < 16; j++) {
            mx0 = fmaxf(mx0, fmaxf(sf[j][0], sf[j][1]));
            mx1 = fmaxf(mx1, fmaxf(sf[j][2], sf[j][3]));
        }
        mx0 = fmaxf(mx0, __shfl_xor_sync(0xffffffffu, mx0, 1));
        mx0 = fmaxf(mx0, __shfl_xor_sync(0xffffffffu, mx0, 2));
        mx1 = fmaxf(mx1, __shfl_xor_sync(0xffffffffu, mx1, 1));
        mx1 = fmaxf(mx1, __shfl_xor_sync(0xffffffffu, mx1, 2));
        float nM0 = fmaxf(M0, mx0), nM1 = fmaxf(M1, mx1);
        float corr0 = fast_exp2(CE * (M0 - nM0));
        float corr1 = fast_exp2(CE * (M1 - nM1));

        // exp + pack directly into PV A-fragments (FA2 layout identity):
        // pa[k2] covers k-block [16k2,16k2+16): a0=(g, blk 2k2), a1=(g+8, blk 2k2),
        // a2=(g, blk 2k2+1), a3=(g+8, blk 2k2+1)
        uint32_t pa[8][4];
        float s0 = 0.f, s1 = 0.f;
        #pragma unroll
        for (int k2 = 0; k2 < 8; k2++) {
            float p00 = fast_exp2(CE * (sf[2*k2][0]   - nM0));
            float p01 = fast_exp2(CE * (sf[2*k2][1]   - nM0));
            float p02 = fast_exp2(CE * (sf[2*k2][2]   - nM1));
            float p03 = fast_exp2(CE * (sf[2*k2][3]   - nM1));
            float p10 = fast_exp2(CE * (sf[2*k2+1][0] - nM0));
            float p11 = fast_exp2(CE * (sf[2*k2+1][1] - nM0));
            float p12 = fast_exp2(CE * (sf[2*k2+1][2] - nM1));
            float p13 = fast_exp2(CE * (sf[2*k2+1][3] - nM1));
            s0 += p00 + p01 + p10 + p11;
            s1 += p02 + p03 + p12 + p13;
            pa[k2][0] = pack_h2(p00, p01);
            pa[k2][1] = pack_h2(p02, p03);
            pa[k2][2] = pack_h2(p10, p11);
            pa[k2][3] = pack_h2(p12, p13);
        }
        s0 += __shfl_xor_sync(0xffffffffu, s0, 1);
        s0 += __shfl_xor_sync(0xffffffffu, s0, 2);
        s1 += __shfl_xor_sync(0xffffffffu, s1, 1);
        s1 += __shfl_xor_sync(0xffffffffu, s1, 2);
        L0 = L0 * corr0 + s0;
        L1 = L1 * corr1 + s1;
        M0 = nM0; M1 = nM1;

        #pragma unroll
        for (int j = 0; j < 8; j++) {
            of[j][0] *= corr0; of[j][1] *= corr0;
            of[j][2] *= corr1; of[j][3] *= corr1;
        }

        // O += P @ V (B = V^T via ldmatrix.trans)
        #pragma unroll
        for (int k2 = 0; k2 < 8; k2++) {
            #pragma unroll
            for (int jp = 0; jp < 4; jp++) {
                int vrow = k2 * 16 + (lane & 15);
                uint32_t vaddr = vb +
                    SWZ((uint32_t)(vrow * 128 + jp * 32 + (lane >> 4) * 16));
                uint32_t r0, r1, r2, r3;
                LDSM_X4_T(r0, r1, r2, r3, vaddr);
                mma_f16(of[jp * 2],     pa[k2][0], pa[k2][1], pa[k2][2], pa[k2][3], r0, r1);
                mma_f16(of[jp * 2 + 1], pa[k2][0], pa[k2][1], pa[k2][2], pa[k2][3], r2, r3);
            }
        }
    }

    float i0 = 1.0f / L0, i1 = 1.0f / L1;
    __half* Og = g_att_h + ((long long)(b * N_ + q0 + w * 16)) * D_ + h * HD_;
    #pragma unroll
    for (int j = 0; j < 8; j++) {
        *reinterpret_cast<__half2*>(&Og[(long long)gid * D_ + j * 8 + tig * 2]) =
            __floats2half2_rn(of[j][0] * i0, of[j][1] * i0);
        *reinterpret_cast<__half2*>(&Og[(long long)(gid + 8) * D_ + j * 8 + tig * 2]) =
            __floats2half2_rn(of[j][2] * i1, of[j][3] * i1);
    }
}

// ---------------- small kernels ----------------
__global__ void f2h_kernel(const float* __restrict__ src, __half* __restrict__ dst,
                           int n8) {
    int i = blockIdx.x * blockDim.x + threadIdx.x;
    if (i >= n8) return;
    const float4* s4 = reinterpret_cast<const float4*>(src);
    float4 a = s4[i * 2], b = s4[i * 2 + 1];
    union { __half2 h[4]; uint4 u; } pack;
    pack.h[0] = __floats2half2_rn(a.x, a.y);
    pack.h[1] = __floats2half2_rn(a.z, a.w);
    pack.h[2] = __floats2half2_rn(b.x, b.y);
    pack.h[3] = __floats2half2_rn(b.z, b.w);
    reinterpret_cast<uint4*>(dst)[i] = pack.u;
}

// LN1: xn = LN(x) (f32 + half), init counters
__global__ void ln1_kernel(const float* __restrict__ x,
                           const float* __restrict__ g, const float* __restrict__ b) {
    __shared__ float sh[33];
    long long row = blockIdx.x;
    int tid = threadIdx.x;
    if (blockIdx.x == 0 && tid < E_) g_cnt[tid] = 0;
    float v[4];
    #pragma unroll
    for (int i = 0; i < 4; i++) v[i] = x[row * D_ + tid + 256 * i];
    float s = block_reduce_sum(v[0] + v[1] + v[2] + v[3], sh);
    float m = s * (1.0f / D_);
    float q = 0.f;
    #pragma unroll
    for (int i = 0; i < 4; i++) { float d = v[i] - m; q += d * d; }
    q = block_reduce_sum(q, sh);
    float rstd = rsqrtf(q * (1.0f / D_) + 1e-5f);
    #pragma unroll
    for (int i = 0; i < 4; i++) {
        int c = tid + 256 * i;
        float r = (v[i] - m) * rstd * g[c] + b[c];
        g_xn[row * D_ + c]   = r;
        g_xn_h[row * D_ + c] = __float2half(r);
    }
}

// LN2 fused with combine_o: o = w0*projO[a0] + w1*projO[a1]; h = x + o;
// hn = LN(h) -> half; h stored f32.
__global__ void ln2_fused_kernel(const float* __restrict__ x,
                                 const float* __restrict__ g, const float* __restrict__ b) {
    __shared__ float sh[33];
    long long row = blockIdx.x;
    int tid = threadIdx.x;
    int a0 = g_aidx[row * 2 + 0], a1 = g_aidx[row * 2 + 1];
    float w0 = g_topw[row * 2 + 0], w1 = g_topw[row * 2 + 1];
    const __half* pO = g_projQKV;
    long long r0 = (long long)a0 * D_, r1 = (long long)a1 * D_;
    float v[4];
    #pragma unroll
    for (int i = 0; i < 4; i++) {
        int c = tid + 256 * i;
        float o = w0 * __half2float(pO[r0 + c]) + w1 * __half2float(pO[r1 + c]);
        v[i] = x[row * D_ + c] + o;
        g_h[row * D_ + c] = v[i];
    }
    float s = block_reduce_sum(v[0] + v[1] + v[2] + v[3], sh);
    float m = s * (1.0f / D_);
    float q = 0.f;
    #pragma unroll
    for (int i = 0; i < 4; i++) { float d = v[i] - m; q += d * d; }
    q = block_reduce_sum(q, sh);
    float rstd = rsqrtf(q * (1.0f / D_) + 1e-5f);
    #pragma unroll
    for (int i = 0; i < 4; i++) {
        int c = tid + 256 * i;
        g_hn_h[row * D_ + c] = __float2half((v[i] - m) * rstd * g[c] + b[c]);
    }
}

__global__ void router_kernel(const float* __restrict__ Wr) {
    int warp = (blockIdx.x * blockDim.x + threadIdx.x) >> 5;
    int lane = threadIdx.x & 31;
    if (warp >= T_) return;
    const float* xr = g_xn + (long long)warp * D_;
    float acc[E_];
    #pragma unroll
    for (int e = 0; e < E_; e++) acc[e] = 0.f;
    for (int i = lane; i < D_; i += 32) {
        float xv = xr[i];
        #pragma unroll
        for (int e = 0; e < E_; e++) acc[e] += xv * Wr[e * D_ + i];
    }
    #pragma unroll
    for (int e = 0; e < E_; e++)
        #pragma unroll
        for (int o = 16; o; o >>= 1) acc[e] += __shfl_xor_sync(0xffffffffu, acc[e], o);
    if (lane == 0) {
        float mx = acc[0];
        #pragma unroll
        for (int e = 1; e < E_; e++) mx = fmaxf(mx, acc[e]);
        float p[E_], s = 0.f;
        #pragma unroll
        for (int e = 0; e < E_; e++) { p[e] = expf(acc[e] - mx); s += p[e]; }
        float inv = 1.0f / s;
        #pragma unroll
        for (int e = 0; e < E_; e++) { p[e] *= inv; g_probs[warp * E_ + e] = p[e]; }
        int i0 = 0;
        #pragma unroll
        for (int e = 1; e < E_; e++) if (p[e] > p[i0]) i0 = e;
        int i1 = (i0 == 0) ? 1 : 0;
        #pragma unroll
        for (int e = 0; e < E_; e++) if (e != i0 && p[e] > p[i1]) i1 = e;
        float v0 = p[i0], v1 = p[i1];
        float wsum = v0 + v1 + 1e-6f;
        g_topi[warp * 2 + 0] = i0;
        g_topi[warp * 2 + 1] = i1;
        g_topw[warp * 2 + 0] = v0 / wsum;
        g_topw[warp * 2 + 1] = v1 / wsum;
        atomicAdd(&g_cnt[i0], 1);
        atomicAdd(&g_cnt[i1], 1);
    }
}

// merged scan + scatter + load-balance loss (single block)
__global__ void scan_scatter_lb_kernel(float* __restrict__ out, int out_size) {
    __shared__ float sh[256];
    int tid = threadIdx.x;
    if (tid == 0) {
        int s = 0;
        for (int e = 0; e < E_; e++) { g_off[e] = s; s += g_cnt[e]; g_ctr[e] = 0; }
        g_off[E_] = s;
    }
    __syncthreads();
    for (int idx = tid; idx < A_; idx += 256) {
        int e = g_topi[idx];
        int pos = g_off[e] + atomicAdd(&g_ctr[e], 1);
        g_tok[pos]  = idx >> 1;
        g_aidx[idx] = pos;
    }
    // load-balance loss
    float pl[E_];
    #pragma unroll
    for (int e = 0; e < E_; e++) pl[e] = 0.f;
    for (int t = tid; t < T_; t += 256)
        #pragma unroll
        for (int e = 0; e < E_; e++) pl[e] += g_probs[t * E_ + e];
    float pe[E_];
    for (int e = 0; e < E_; e++) {
        sh[tid] = pl[e];
        __syncthreads();
        for (int o = 128; o; o >>= 1) {
            if (tid < o) sh[tid] += sh[tid + o];
            __syncthreads();
        }
        pe[e] = sh[0];
        __syncthreads();
    }
    if (tid == 0) {
        float lb = 0.f;
        float denom = (float)A_ + 1e-6f;
        for (int e = 0; e < E_; e++)
            lb += ((float)g_cnt[e] / denom) * pe[e];
        lb *= (float)E_;
        if (out_size > (int)TD) out[TD] = lb;
    }
}

// combine Q,K,V (half proj -> half q/k/v)
__global__ void combine_qkv_kernel() {
    long long t = blockIdx.x;
    int tid = threadIdx.x;
    int a0 = g_aidx[t * 2 + 0], a1 = g_aidx[t * 2 + 1];
    float w0 = g_topw[t * 2 + 0], w1 = g_topw[t * 2 + 1];
    const __half2* pQ = reinterpret_cast<const __half2*>(g_projQKV);
    const __half2* pK = reinterpret_cast<const __half2*>(g_projQKV + (long long)A_ * D_);
    const __half2* pV = reinterpret_cast<const __half2*>(g_projQKV + 2LL * A_ * D_);
    long long r0 = (long long)a0 * (D_ / 2), r1 = (long long)a1 * (D_ / 2);
    long long tb = t * (D_ / 2);
    #pragma unroll
    for (int i = 0; i < 2; i++) {
        int c = tid + 256 * i;
        float2 q0 = __half22float2(pQ[r0 + c]), q1 = __half22float2(pQ[r1 + c]);
        float2 k0 = __half22float2(pK[r0 + c]), k1 = __half22float2(pK[r1 + c]);
        float2 v0 = __half22float2(pV[r0 + c]), v1 = __half22float2(pV[r1 + c]);
        reinterpret_cast<__half2*>(g_q_h)[tb + c] =
            __floats2half2_rn(w0 * q0.x + w1 * q1.x, w0 * q0.y + w1 * q1.y);
        reinterpret_cast<__half2*>(g_k_h)[tb + c] =
            __floats2half2_rn(w0 * k0.x + w1 * k1.x, w0 * k0.y + w1 * k1.y);
        reinterpret_cast<__half2*>(g_v_h)[tb + c] =
            __floats2half2_rn(w0 * v0.x + w1 * v1.x, w0 * v0.y + w1 * v1.y);
    }
}

// ---------------- host launch ----------------
extern "C" void kernel_launch(void* const* d_in, const int* in_sizes, int n_in,
                              void* d_out, int out_size) {
    const float* x   = (const float*)d_in[0];
    const float* Wr  = (const float*)d_in[1];
    const float* Wq  = (const float*)d_in[2];
    const float* Wk  = (const float*)d_in[3];
    const float* Wv  = (const float*)d_in[4];
    const float* Wo  = (const float*)d_in[5];
    const float* W1  = (const float*)d_in[6];
    const float* b1  = (const float*)d_in[7];
    const float* W2  = (const float*)d_in[8];
    const float* b2  = (const float*)d_in[9];
    const float* g1  = (const float*)d_in[10];
    const float* be1 = (const float*)d_in[11];
    const float* g2  = (const float*)d_in[12];
    const float* be2 = (const float*)d_in[13];
    float* out = (float*)d_out;

    float  *p_h;
    __half *p_xn_h, *p_att_h, *p_hn_h, *p_ff1_h, *p_projQKV;
    __half *p_Wqkv_h, *p_Wo_h, *p_W1_h, *p_W2_h;
    int *p_off, *p_tok;
    cudaGetSymbolAddress((void**)&p_xn_h,   g_xn_h);
    cudaGetSymbolAddress((void**)&p_projQKV,g_projQKV);
    cudaGetSymbolAddress((void**)&p_att_h,  g_att_h);
    cudaGetSymbolAddress((void**)&p_h,      g_h);
    cudaGetSymbolAddress((void**)&p_hn_h,   g_hn_h);
    cudaGetSymbolAddress((void**)&p_ff1_h,  g_ff1_h);
    cudaGetSymbolAddress((void**)&p_Wqkv_h, g_Wqkv_h);
    cudaGetSymbolAddress((void**)&p_Wo_h,   g_Wo_h);
    cudaGetSymbolAddress((void**)&p_W1_h,   g_W1_h);
    cudaGetSymbolAddress((void**)&p_W2_h,   g_W2_h);
    cudaGetSymbolAddress((void**)&p_off,    g_off);
    cudaGetSymbolAddress((void**)&p_tok,    g_tok);

    const long long EDD = (long long)E_ * D_ * D_;
    const long long DD  = (long long)D_ * D_;
    cudaFuncSetAttribute(gemm_h,
                         cudaFuncAttributeMaxDynamicSharedMemorySize, GH_SMEM);
    cudaFuncSetAttribute(flash_attn_h,
                         cudaFuncAttributeMaxDynamicSharedMemorySize, FAH_SMEM);

    // weight conversions
    {
        int n8 = (int)(EDD / 8);
        int blk = (n8 + 255) / 256;
        f2h_kernel<<<blk, 256>>>(Wq, p_Wqkv_h, n8);
        f2h_kernel<<<blk, 256>>>(Wk, p_Wqkv_h + EDD, n8);
        f2h_kernel<<<blk, 256>>>(Wv, p_Wqkv_h + 2 * EDD, n8);
        f2h_kernel<<<blk, 256>>>(Wo, p_Wo_h, n8);
        int nf = (int)((long long)FF_ * D_ * D_ / 8);
        int blkf = (nf + 255) / 256;
        f2h_kernel<<<blkf, 256>>>(W1, p_W1_h, nf);
        f2h_kernel<<<blkf, 256>>>(W2, p_W2_h, nf);
    }

    ln1_kernel<<<T_, 256>>>(x, g1, be1);
    router_kernel<<<T_ / 8, 256>>>(Wr);
    scan_scatter_lb_kernel<<<1, 256>>>(out, out_size);

    // merged grouped QKV GEMM: z = p*E + e
    gemm_h<<<dim3(D_ / 128, A_ / 128, 3 * E_), 256, GH_SMEM>>>(
        p_xn_h, p_Wqkv_h, nullptr, p_projQKV,
        D_, D_, D_, D_, E_, EDD, DD, (long long)A_ * D_,
        p_off, p_tok, A_, 0, nullptr, nullptr);
    combine_qkv_kernel<<<T_, 256>>>();

    // fp16 flash attention
    flash_attn_h<<<dim3(N_ / 128, B_ * H_), 256, FAH_SMEM>>>();

    // grouped O projection (into proj slot 0); combine fused into LN2
    gemm_h<<<dim3(D_ / 128, A_ / 128, E_), 256, GH_SMEM>>>(
        p_att_h, p_Wo_h, nullptr, p_projQKV,
        D_, D_, D_, D_, E_, 0, DD, 0,
        p_off, p_tok, A_, 0, nullptr, nullptr);

    // h = x + combine(projO) ; hn = LN2(h) -> half
    ln2_fused_kernel<<<T_, 256>>>(x, g2, be2);

    // FFN1
    gemm_h<<<dim3(FF_ * D_ / 128, T_ / 128, 1), 256, GH_SMEM>>>(
        p_hn_h, p_W1_h, nullptr, p_ff1_h,
        D_, D_, D_, FF_ * D_, 1, 0, 0, 0,
        nullptr, nullptr, T_, 2, b1, nullptr);

    // FFN2 -> d_out
    gemm_h<<<dim3(D_ / 128, T_ / 128, 1), 256, GH_SMEM>>>(
        p_ff1_h, p_W2_h, out, nullptr,
        FF_ * D_, FF_ * D_, FF_ * D_, D_, 1, 0, 0, 0,
        nullptr, nullptr, T_, 3, b2, p_h);
}

// round 8
// speedup vs baseline: 2.8635x; 1.0860x over previous
#include <cuda_runtime.h>
#include <cuda_fp16.h>
#include <math.h>
#include <stdint.h>

// ---------------- problem constants ----------------
#define B_   4
#define N_   1024
#define D_   1024
#define H_   16
#define E_   12
#define KTOP 2
#define FF_  4
#define HD_  64
#define T_   (B_*N_)
#define A_   (T_*KTOP)
#define TD   ((long long)T_*D_)

// ---------------- static device scratch ----------------
__device__ __half g_xn_h [T_*D_];
__device__ float  g_probs[T_*E_];
__device__ int    g_topi [T_*KTOP];
__device__ float  g_topw [T_*KTOP];
__device__ int    g_cnt  [E_];
__device__ int    g_off  [E_+1];
__device__ int    g_ctr  [E_];
__device__ int    g_tok  [A_];
__device__ int    g_aidx [T_*KTOP];
__device__ __half g_projQKV[3LL*A_*D_];   // Q | K | V slots; O reuses slot 0
__device__ __half g_q_h  [T_*D_];
__device__ __half g_k_h  [T_*D_];
__device__ __half g_v_h  [T_*D_];
__device__ __half g_att_h[T_*D_];
__device__ float  g_h    [T_*D_];
__device__ __half g_hn_h [T_*D_];
__device__ __half g_ff1_h[T_*FF_*D_];
// half weight shadows
__device__ __half g_Wqkv_h[3LL*E_*D_*D_];
__device__ __half g_Wo_h  [(long long)E_*D_*D_];
__device__ __half g_W1_h  [(long long)FF_*D_*D_];
__device__ __half g_W2_h  [(long long)FF_*D_*D_];

// ---------------- PTX helpers ----------------
__device__ __forceinline__ uint32_t smem_u32(const void* p) {
    uint32_t a;
    asm("{ .reg .u64 t; cvta.to.shared.u64 t, %1; cvt.u32.u64 %0, t; }"
        : "=r"(a) : "l"(p));
    return a;
}
__device__ __forceinline__ void cp_async16s(uint32_t s, const void* g, int sz) {
    asm volatile("cp.async.cg.shared.global [%0], [%1], 16, %2;\n"
                 :: "r"(s), "l"(g), "r"(sz));
}
__device__ __forceinline__ void cp_commit() {
    asm volatile("cp.async.commit_group;\n");
}
template<int NN>
__device__ __forceinline__ void cp_wait() {
    asm volatile("cp.async.wait_group %0;\n" :: "n"(NN));
}
#define SWZ(o) ((o) ^ (((o) >> 3) & 0x70))

#define LDSM_X4(r0, r1, r2, r3, addr) \
    asm volatile("ldmatrix.sync.aligned.m8n8.x4.shared.b16 {%0,%1,%2,%3}, [%4];" \
        : "=r"(r0), "=r"(r1), "=r"(r2), "=r"(r3) : "r"(addr))
#define LDSM_X4_T(r0, r1, r2, r3, addr) \
    asm volatile("ldmatrix.sync.aligned.m8n8.x4.trans.shared.b16 {%0,%1,%2,%3}, [%4];" \
        : "=r"(r0), "=r"(r1), "=r"(r2), "=r"(r3) : "r"(addr))

__device__ __forceinline__ void mma_f16(float c[4],
        uint32_t a0, uint32_t a1, uint32_t a2, uint32_t a3,
        uint32_t b0, uint32_t b1) {
    asm volatile(
        "mma.sync.aligned.m16n8k16.row.col.f32.f16.f16.f32 "
        "{%0,%1,%2,%3}, {%4,%5,%6,%7}, {%8,%9}, {%0,%1,%2,%3};"
        : "+f"(c[0]), "+f"(c[1]), "+f"(c[2]), "+f"(c[3])
        : "r"(a0), "r"(a1), "r"(a2), "r"(a3), "r"(b0), "r"(b1));
}
__device__ __forceinline__ float fast_exp2(float x) {
    float y;
    asm("ex2.approx.f32 %0, %1;" : "=f"(y) : "f"(x));
    return y;
}
__device__ __forceinline__ uint32_t pack_h2(float a, float b) {
    __half2 h = __floats2half2_rn(a, b);
    uint32_t u;
    asm("mov.b32 %0, %1;" : "=r"(u) : "r"(*reinterpret_cast<uint32_t*>(&h)));
    return u;
}
__device__ __forceinline__ float gelu_tanh(float x) {
    float x3 = x * x * x;
    return 0.5f * x * (1.0f + tanhf(0.7978845608028654f * (x + 0.044715f * x3)));
}
__device__ __forceinline__ float block_reduce_sum(float v, float* sh) {
    int tid = threadIdx.x;
    #pragma unroll
    for (int o = 16; o; o >>= 1) v += __shfl_xor_sync(0xffffffffu, v, o);
    if ((tid & 31) == 0) sh[tid >> 5] = v;
    __syncthreads();
    if (tid < 32) {
        v = (tid < (int)(blockDim.x >> 5)) ? sh[tid] : 0.0f;
        #pragma unroll
        for (int o = 16; o; o >>= 1) v += __shfl_xor_sync(0xffffffffu, v, o);
        if (tid == 0) sh[0] = v;
    }
    __syncthreads();
    float r = sh[0];
    __syncthreads();
    return r;
}

// ================= fp16 HMMA GEMM (2 CTAs/SM) =================
#define GH_STAGES 3
#define GH_STAGE_BYTES 32768
#define GH_SMEM (GH_STAGES*GH_STAGE_BYTES)

__global__ void __launch_bounds__(256, 2)
gemm_h(const __half* __restrict__ A, const __half* __restrict__ Bw,
       float* __restrict__ C, __half* __restrict__ Ch,
       int K, int lda, int ldb, int ldc,
       int zdiv, long long bz1, long long bz2, long long cz1,
       const int* __restrict__ seg_off, const int* __restrict__ tok,
       int Mfull, int epi,
       const float* __restrict__ bias, const float* __restrict__ resid) {
    extern __shared__ char smem[];
    uint32_t sb = smem_u32(smem);
    int tid = threadIdx.x, lane = tid & 31, warp = tid >> 5;
    int gid = lane >> 2, tig = lane & 3;
    int wm = warp & 1, wn = warp >> 1;

    int z  = blockIdx.z;
    int z1 = z / zdiv;
    int z2 = z - z1 * zdiv;
    const __half* Bb = Bw + z1 * bz1 + z2 * bz2;
    float*  Cb  = C;
    __half* Chb = Ch ? Ch + z1 * cz1 : (__half*)0;

    int Mseg = Mfull;
    const int* grows = nullptr;
    if (seg_off) {
        int s = seg_off[z2];
        Mseg  = seg_off[z2 + 1] - s;
        grows = tok + s;
        if (Chb) Chb += (long long)s * ldc;
        if (Cb)  Cb  += (long long)s * ldc;
    }
    int m0 = blockIdx.y * 128;
    if (m0 >= Mseg) return;
    int n0 = blockIdx.x * 128;

    float acc[4][4][4];
    #pragma unroll
    for (int i = 0; i < 4; i++)
        #pragma unroll
        for (int j = 0; j < 4; j++)
            #pragma unroll
            for (int u = 0; u < 4; u++) acc[i][j][u] = 0.0f;

    int nk = K / 64;

    auto issue = [&](int it) {
        int st = it % GH_STAGES;
        uint32_t abase = sb + st * GH_STAGE_BYTES;
        uint32_t bbase = abase + 16384;
        int k0 = it * 64;
        #pragma unroll
        for (int c = 0; c < 4; c++) {
            int ch = tid + 256 * c;
            int row = ch >> 3, kc = ch & 7;
            int gm = m0 + row;
            uint32_t dst = abase + SWZ((uint32_t)(row * 128 + kc * 16));
            const __half* src = A;
            int sz = 0;
            if (gm < Mseg) {
                long long rr = grows ? (long long)grows[gm] : (long long)gm;
                src = A + rr * (long long)lda + k0 + kc * 8;
                sz = 16;
            }
            cp_async16s(dst, src, sz);
        }
        #pragma unroll
        for (int c = 0; c < 4; c++) {
            int ch = tid + 256 * c;
            int row = ch >> 3, kc = ch & 7;
            uint32_t dst = bbase + SWZ((uint32_t)(row * 128 + kc * 16));
            cp_async16s(dst, Bb + (long long)(n0 + row) * ldb + k0 + kc * 8, 16);
        }
        cp_commit();
    };

    issue(0);
    if (nk > 1) issue(1);

    for (int it = 0; it < nk; it++) {
        if (it < nk - 1) cp_wait<1>(); else cp_wait<0>();
        __syncthreads();
        if (it + 2 < nk) issue(it + 2);

        int st = it % GH_STAGES;
        uint32_t abase = sb + st * GH_STAGE_BYTES;
        uint32_t bbase = abase + 16384;

        #pragma unroll
        for (int ks = 0; ks < 4; ks++) {
            uint32_t af[4][4];
            #pragma unroll
            for (int i = 0; i < 4; i++) {
                int row = wm * 64 + i * 16 + (lane & 15);
                uint32_t addr = abase +
                    SWZ((uint32_t)(row * 128 + ks * 32 + (lane >> 4) * 16));
                LDSM_X4(af[i][0], af[i][1], af[i][2], af[i][3], addr);
            }
            uint32_t bf[4][2];
            #pragma unroll
            for (int jp = 0; jp < 2; jp++) {
                int nrow = wn * 32 + jp * 16 + (lane & 15);
                uint32_t addr = bbase +
                    SWZ((uint32_t)(nrow * 128 + ks * 32 + (lane >> 4) * 16));
                uint32_t r0, r1, r2, r3;
                LDSM_X4(r0, r1, r2, r3, addr);
                bf[jp * 2][0] = r0; bf[jp * 2 + 1][0] = r1;
                bf[jp * 2][1] = r2; bf[jp * 2 + 1][1] = r3;
            }
            #pragma unroll
            for (int i = 0; i < 4; i++)
                #pragma unroll
                for (int j = 0; j < 4; j++)
                    mma_f16(acc[i][j], af[i][0], af[i][1], af[i][2], af[i][3],
                            bf[j][0], bf[j][1]);
        }
        __syncthreads();
    }

    #pragma unroll
    for (int i = 0; i < 4; i++)
        #pragma unroll
        for (int j = 0; j < 4; j++)
            #pragma unroll
            for (int h2 = 0; h2 < 2; h2++) {
                int r  = wm * 64 + i * 16 + gid + h2 * 8;
                int gm = m0 + r;
                if (gm >= Mseg) continue;
                int c  = wn * 32 + j * 8 + tig * 2;
                int gn = n0 + c;
                float v0 = acc[i][j][h2 * 2 + 0];
                float v1 = acc[i][j][h2 * 2 + 1];
                long long off = (long long)gm * ldc + gn;
                if (epi == 0) {
                    *reinterpret_cast<__half2*>(Chb + off) =
                        __floats2half2_rn(v0, v1);
                } else if (epi == 2) {
                    v0 = gelu_tanh(v0 + bias[gn]);
                    v1 = gelu_tanh(v1 + bias[gn + 1]);
                    *reinterpret_cast<__half2*>(Chb + off) =
                        __floats2half2_rn(v0, v1);
                } else {   // epi == 3
                    float2 rr = *reinterpret_cast<const float2*>(resid + off);
                    v0 = v0 + bias[gn] + rr.x;
                    v1 = v1 + bias[gn + 1] + rr.y;
                    *reinterpret_cast<float2*>(Cb + off) = make_float2(v0, v1);
                }
            }
}

// ================= fp16 flash attention (FA2 register P-reuse) =================
#define FAH_KS(buf) (8192 + (buf)*16384)
#define FAH_VS(buf) (16384 + (buf)*16384)
#define FAH_SMEM (40960*2)   // 81920 B

__global__ void __launch_bounds__(256)
flash_attn_h() {
    extern __shared__ __half smh[];
    uint32_t sb = smem_u32(smh);

    int bh = blockIdx.y;
    int b = bh >> 4, h = bh & 15;
    int q0 = blockIdx.x * 128;
    int tid = threadIdx.x, lane = tid & 31, w = tid >> 5;
    int gid = lane >> 2, tig = lane & 3;

    const __half* Qg = g_q_h + ((long long)(b * N_ + q0)) * D_ + h * HD_;

    auto issue_kv = [&](int t) {
        int buf = t & 1;
        const __half* Kg = g_k_h + ((long long)(b * N_ + t * 128)) * D_ + h * HD_;
        const __half* Vg = g_v_h + ((long long)(b * N_ + t * 128)) * D_ + h * HD_;
        uint32_t kb = sb + FAH_KS(buf) * 2;
        uint32_t vb = sb + FAH_VS(buf) * 2;
        #pragma unroll
        for (int p = 0; p < 4; p++) {
            int ch = tid + 256 * p;
            int r = ch >> 3, c16 = ch & 7;
            uint32_t doff = SWZ((uint32_t)(r * 128 + c16 * 16));
            cp_async16s(kb + doff, Kg + (long long)r * D_ + c16 * 8, 16);
            cp_async16s(vb + doff, Vg + (long long)r * D_ + c16 * 8, 16);
        }
        cp_commit();
    };

    {
        uint32_t qb = sb;
        #pragma unroll
        for (int p = 0; p < 4; p++) {
            int ch = tid + 256 * p;
            int r = ch >> 3, c16 = ch & 7;
            uint32_t doff = SWZ((uint32_t)(r * 128 + c16 * 16));
            cp_async16s(qb + doff, Qg + (long long)r * D_ + c16 * 8, 16);
        }
        cp_commit();
        issue_kv(0);
    }

    uint32_t qf[4][4];
    cp_wait<1>();
    __syncthreads();
    #pragma unroll
    for (int ks = 0; ks < 4; ks++) {
        int row = w * 16 + (lane & 15);
        uint32_t addr = sb + SWZ((uint32_t)(row * 128 + ks * 32 + (lane >> 4) * 16));
        LDSM_X4(qf[ks][0], qf[ks][1], qf[ks][2], qf[ks][3], addr);
    }

    float of[8][4];
    #pragma unroll
    for (int j = 0; j < 8; j++)
        #pragma unroll
        for (int u = 0; u < 4; u++) of[j][u] = 0.0f;
    float M0 = -1e30f, M1 = -1e30f, L0 = 0.f, L1 = 0.f;
    const float CE = 0.125f * 1.4426950408889634f;

    for (int t = 0; t < 8; t++) {
        __syncthreads();
        if (t < 7) issue_kv(t + 1);
        if (t < 7) cp_wait<1>(); else cp_wait<0>();
        __syncthreads();

        int buf = t & 1;
        uint32_t kb = sb + FAH_KS(buf) * 2;
        uint32_t vb = sb + FAH_VS(buf) * 2;

        float sf[16][4];
        #pragma unroll
        for (int j = 0; j < 16; j++)
            #pragma unroll
            for (int u = 0; u < 4; u++) sf[j][u] = 0.0f;
        #pragma unroll
        for (int ks = 0; ks < 4; ks++) {
            #pragma unroll
            for (int jj = 0; jj < 8; jj++) {
                int nrow = jj * 16 + (lane & 15);
                uint32_t addr = kb +
                    SWZ((uint32_t)(nrow * 128 + ks * 32 + (lane >> 4) * 16));
                uint32_t r0, r1, r2, r3;
                LDSM_X4(r0, r1, r2, r3, addr);
                mma_f16(sf[jj * 2],     qf[ks][0], qf[ks][1], qf[ks][2], qf[ks][3], r0, r2);
                mma_f16(sf[jj * 2 + 1], qf[ks][0], qf[ks][1], qf[ks][2], qf[ks][3], r1, r3);
            }
        }

        float mx0 = -1e30f, mx1 = -1e30f;
        #pragma unroll
        for (int j = 0; j < 16; j++) {
            mx0 = fmaxf(mx0, fmaxf(sf[j][0], sf[j][1]));
            mx1 = fmaxf(mx1, fmaxf(sf[j][2], sf[j][3]));
        }
        mx0 = fmaxf(mx0, __shfl_xor_sync(0xffffffffu, mx0, 1));
        mx0 = fmaxf(mx0, __shfl_xor_sync(0xffffffffu, mx0, 2));
        mx1 = fmaxf(mx1, __shfl_xor_sync(0xffffffffu, mx1, 1));
        mx1 = fmaxf(mx1, __shfl_xor_sync(0xffffffffu, mx1, 2));
        float nM0 = fmaxf(M0, mx0), nM1 = fmaxf(M1, mx1);
        float corr0 = fast_exp2(CE * (M0 - nM0));
        float corr1 = fast_exp2(CE * (M1 - nM1));

        uint32_t pa[8][4];
        float s0 = 0.f, s1 = 0.f;
        #pragma unroll
        for (int k2 = 0; k2 < 8; k2++) {
            float p00 = fast_exp2(CE * (sf[2*k2][0]   - nM0));
            float p01 = fast_exp2(CE * (sf[2*k2][1]   - nM0));
            float p02 = fast_exp2(CE * (sf[2*k2][2]   - nM1));
            float p03 = fast_exp2(CE * (sf[2*k2][3]   - nM1));
            float p10 = fast_exp2(CE * (sf[2*k2+1][0] - nM0));
            float p11 = fast_exp2(CE * (sf[2*k2+1][1] - nM0));
            float p12 = fast_exp2(CE * (sf[2*k2+1][2] - nM1));
            float p13 = fast_exp2(CE * (sf[2*k2+1][3] - nM1));
            s0 += p00 + p01 + p10 + p11;
            s1 += p02 + p03 + p12 + p13;
            pa[k2][0] = pack_h2(p00, p01);
            pa[k2][1] = pack_h2(p02, p03);
            pa[k2][2] = pack_h2(p10, p11);
            pa[k2][3] = pack_h2(p12, p13);
        }
        s0 += __shfl_xor_sync(0xffffffffu, s0, 1);
        s0 += __shfl_xor_sync(0xffffffffu, s0, 2);
        s1 += __shfl_xor_sync(0xffffffffu, s1, 1);
        s1 += __shfl_xor_sync(0xffffffffu, s1, 2);
        L0 = L0 * corr0 + s0;
        L1 = L1 * corr1 + s1;
        M0 = nM0; M1 = nM1;

        #pragma unroll
        for (int j = 0; j < 8; j++) {
            of[j][0] *= corr0; of[j][1] *= corr0;
            of[j][2] *= corr1; of[j][3] *= corr1;
        }

        #pragma unroll
        for (int k2 = 0; k2 < 8; k2++) {
            #pragma unroll
            for (int jp = 0; jp < 4; jp++) {
                int vrow = k2 * 16 + (lane & 15);
                uint32_t vaddr = vb +
                    SWZ((uint32_t)(vrow * 128 + jp * 32 + (lane >> 4) * 16));
                uint32_t r0, r1, r2, r3;
                LDSM_X4_T(r0, r1, r2, r3, vaddr);
                mma_f16(of[jp * 2],     pa[k2][0], pa[k2][1], pa[k2][2], pa[k2][3], r0, r1);
                mma_f16(of[jp * 2 + 1], pa[k2][0], pa[k2][1], pa[k2][2], pa[k2][3], r2, r3);
            }
        }
    }

    float i0 = 1.0f / L0, i1 = 1.0f / L1;
    __half* Og = g_att_h + ((long long)(b * N_ + q0 + w * 16)) * D_ + h * HD_;
    #pragma unroll
    for (int j = 0; j < 8; j++) {
        *reinterpret_cast<__half2*>(&Og[(long long)gid * D_ + j * 8 + tig * 2]) =
            __floats2half2_rn(of[j][0] * i0, of[j][1] * i0);
        *reinterpret_cast<__half2*>(&Og[(long long)(gid + 8) * D_ + j * 8 + tig * 2]) =
            __floats2half2_rn(of[j][2] * i1, of[j][3] * i1);
    }
}

// ---------------- small kernels ----------------
// single fused weight converter: 6 segments, 8 floats per chunk
__global__ void f2h_all_kernel(const float* s0, const float* s1, const float* s2,
                               const float* s3, const float* s4, const float* s5,
                               __half* d0, __half* d1, __half* d2,
                               __half* d3, __half* d4, __half* d5,
                               long long c1, long long c2, long long c3,
                               long long c4, long long c5, long long c6) {
    long long i = (long long)blockIdx.x * blockDim.x + threadIdx.x;
    if (i >= c6) return;
    const float* s; __half* d; long long base;
    if      (i < c1) { s = s0; d = d0; base = 0;  }
    else if (i < c2) { s = s1; d = d1; base = c1; }
    else if (i < c3) { s = s2; d = d2; base = c2; }
    else if (i < c4) { s = s3; d = d3; base = c3; }
    else if (i < c5) { s = s4; d = d4; base = c4; }
    else             { s = s5; d = d5; base = c5; }
    long long j = i - base;
    const float4* s4p = reinterpret_cast<const float4*>(s);
    float4 a = s4p[j * 2], bb = s4p[j * 2 + 1];
    union { __half2 h[4]; uint4 u; } pack;
    pack.h[0] = __floats2half2_rn(a.x, a.y);
    pack.h[1] = __floats2half2_rn(a.z, a.w);
    pack.h[2] = __floats2half2_rn(bb.x, bb.y);
    pack.h[3] = __floats2half2_rn(bb.z, bb.w);
    reinterpret_cast<uint4*>(d)[j] = pack.u;
}

// LN1: xn_h = LN(x) (half only), init counters
__global__ void ln1_kernel(const float* __restrict__ x,
                           const float* __restrict__ g, const float* __restrict__ b) {
    __shared__ float sh[33];
    long long row = blockIdx.x;
    int tid = threadIdx.x;
    if (blockIdx.x == 0 && tid < E_) g_cnt[tid] = 0;
    float v[4];
    #pragma unroll
    for (int i = 0; i < 4; i++) v[i] = x[row * D_ + tid + 256 * i];
    float s = block_reduce_sum(v[0] + v[1] + v[2] + v[3], sh);
    float m = s * (1.0f / D_);
    float q = 0.f;
    #pragma unroll
    for (int i = 0; i < 4; i++) { float d = v[i] - m; q += d * d; }
    q = block_reduce_sum(q, sh);
    float rstd = rsqrtf(q * (1.0f / D_) + 1e-5f);
    #pragma unroll
    for (int i = 0; i < 4; i++) {
        int c = tid + 256 * i;
        g_xn_h[row * D_ + c] = __float2half((v[i] - m) * rstd * g[c] + b[c]);
    }
}

// Router with inline LN: one warp per token, f32 end-to-end.
__global__ void router_kernel(const float* __restrict__ x, const float* __restrict__ Wr,
                              const float* __restrict__ g, const float* __restrict__ bb) {
    int warp = (blockIdx.x * blockDim.x + threadIdx.x) >> 5;
    int lane = threadIdx.x & 31;
    if (warp >= T_) return;
    const float* xr = x + (long long)warp * D_;
    float xv[32];
    float s = 0.f;
    #pragma unroll
    for (int ii = 0; ii < 32; ii++) { xv[ii] = xr[lane + 32 * ii]; s += xv[ii]; }
    #pragma unroll
    for (int o = 16; o; o >>= 1) s += __shfl_xor_sync(0xffffffffu, s, o);
    float m = s * (1.0f / D_);
    float q = 0.f;
    #pragma unroll
    for (int ii = 0; ii < 32; ii++) { float d = xv[ii] - m; q += d * d; }
    #pragma unroll
    for (int o = 16; o; o >>= 1) q += __shfl_xor_sync(0xffffffffu, q, o);
    float rstd = rsqrtf(q * (1.0f / D_) + 1e-5f);

    float acc[E_];
    #pragma unroll
    for (int e = 0; e < E_; e++) acc[e] = 0.f;
    #pragma unroll
    for (int ii = 0; ii < 32; ii++) {
        int i = lane + 32 * ii;
        float xn = (xv[ii] - m) * rstd * g[i] + bb[i];
        #pragma unroll
        for (int e = 0; e < E_; e++) acc[e] += xn * Wr[e * D_ + i];
    }
    #pragma unroll
    for (int e = 0; e < E_; e++)
        #pragma unroll
        for (int o = 16; o; o >>= 1) acc[e] += __shfl_xor_sync(0xffffffffu, acc[e], o);
    if (lane == 0) {
        float mx = acc[0];
        #pragma unroll
        for (int e = 1; e < E_; e++) mx = fmaxf(mx, acc[e]);
        float p[E_], ss = 0.f;
        #pragma unroll
        for (int e = 0; e < E_; e++) { p[e] = expf(acc[e] - mx); ss += p[e]; }
        float inv = 1.0f / ss;
        #pragma unroll
        for (int e = 0; e < E_; e++) { p[e] *= inv; g_probs[warp * E_ + e] = p[e]; }
        int i0 = 0;
        #pragma unroll
        for (int e = 1; e < E_; e++) if (p[e] > p[i0]) i0 = e;
        int i1 = (i0 == 0) ? 1 : 0;
        #pragma unroll
        for (int e = 0; e < E_; e++) if (e != i0 && p[e] > p[i1]) i1 = e;
        float v0 = p[i0], v1 = p[i1];
        float wsum = v0 + v1 + 1e-6f;
        g_topi[warp * 2 + 0] = i0;
        g_topi[warp * 2 + 1] = i1;
        g_topw[warp * 2 + 0] = v0 / wsum;
        g_topw[warp * 2 + 1] = v1 / wsum;
        atomicAdd(&g_cnt[i0], 1);
        atomicAdd(&g_cnt[i1], 1);
    }
}

// merged scan + scatter + load-balance loss (single block, 1024 threads)
__global__ void scan_scatter_lb_kernel(float* __restrict__ out, int out_size) {
    __shared__ float sh[1024];
    int tid = threadIdx.x;
    if (tid == 0) {
        int s = 0;
        for (int e = 0; e < E_; e++) { g_off[e] = s; s += g_cnt[e]; g_ctr[e] = 0; }
        g_off[E_] = s;
    }
    __syncthreads();
    for (int idx = tid; idx < A_; idx += 1024) {
        int e = g_topi[idx];
        int pos = g_off[e] + atomicAdd(&g_ctr[e], 1);
        g_tok[pos]  = idx >> 1;
        g_aidx[idx] = pos;
    }
    float pl[E_];
    #pragma unroll
    for (int e = 0; e < E_; e++) pl[e] = 0.f;
    for (int t = tid; t < T_; t += 1024)
        #pragma unroll
        for (int e = 0; e < E_; e++) pl[e] += g_probs[t * E_ + e];
    float pe[E_];
    for (int e = 0; e < E_; e++) {
        sh[tid] = pl[e];
        __syncthreads();
        for (int o = 512; o; o >>= 1) {
            if (tid < o) sh[tid] += sh[tid + o];
            __syncthreads();
        }
        pe[e] = sh[0];
        __syncthreads();
    }
    if (tid == 0) {
        float lb = 0.f;
        float denom = (float)A_ + 1e-6f;
        for (int e = 0; e < E_; e++)
            lb += ((float)g_cnt[e] / denom) * pe[e];
        lb *= (float)E_;
        if (out_size > (int)TD) out[TD] = lb;
    }
}

// combine Q,K,V (half proj -> half q/k/v)
__global__ void combine_qkv_kernel() {
    long long t = blockIdx.x;
    int tid = threadIdx.x;
    int a0 = g_aidx[t * 2 + 0], a1 = g_aidx[t * 2 + 1];
    float w0 = g_topw[t * 2 + 0], w1 = g_topw[t * 2 + 1];
    const __half2* pQ = reinterpret_cast<const __half2*>(g_projQKV);
    const __half2* pK = reinterpret_cast<const __half2*>(g_projQKV + (long long)A_ * D_);
    const __half2* pV = reinterpret_cast<const __half2*>(g_projQKV + 2LL * A_ * D_);
    long long r0 = (long long)a0 * (D_ / 2), r1 = (long long)a1 * (D_ / 2);
    long long tb = t * (D_ / 2);
    #pragma unroll
    for (int i = 0; i < 2; i++) {
        int c = tid + 256 * i;
        float2 q0 = __half22float2(pQ[r0 + c]), q1 = __half22float2(pQ[r1 + c]);
        float2 k0 = __half22float2(pK[r0 + c]), k1 = __half22float2(pK[r1 + c]);
        float2 v0 = __half22float2(pV[r0 + c]), v1 = __half22float2(pV[r1 + c]);
        reinterpret_cast<__half2*>(g_q_h)[tb + c] =
            __floats2half2_rn(w0 * q0.x + w1 * q1.x, w0 * q0.y + w1 * q1.y);
        reinterpret_cast<__half2*>(g_k_h)[tb + c] =
            __floats2half2_rn(w0 * k0.x + w1 * k1.x, w0 * k0.y + w1 * k1.y);
        reinterpret_cast<__half2*>(g_v_h)[tb + c] =
            __floats2half2_rn(w0 * v0.x + w1 * v1.x, w0 * v0.y + w1 * v1.y);
    }
}

// LN2 fused with combine_o
__global__ void ln2_fused_kernel(const float* __restrict__ x,
                                 const float* __restrict__ g, const float* __restrict__ b) {
    __shared__ float sh[33];
    long long row = blockIdx.x;
    int tid = threadIdx.x;
    int a0 = g_aidx[row * 2 + 0], a1 = g_aidx[row * 2 + 1];
    float w0 = g_topw[row * 2 + 0], w1 = g_topw[row * 2 + 1];
    const __half* pO = g_projQKV;
    long long r0 = (long long)a0 * D_, r1 = (long long)a1 * D_;
    float v[4];
    #pragma unroll
    for (int i = 0; i < 4; i++) {
        int c = tid + 256 * i;
        float o = w0 * __half2float(pO[r0 + c]) + w1 * __half2float(pO[r1 + c]);
        v[i] = x[row * D_ + c] + o;
        g_h[row * D_ + c] = v[i];
    }
    float s = block_reduce_sum(v[0] + v[1] + v[2] + v[3], sh);
    float m = s * (1.0f / D_);
    float q = 0.f;
    #pragma unroll
    for (int i = 0; i < 4; i++) { float d = v[i] - m; q += d * d; }
    q = block_reduce_sum(q, sh);
    float rstd = rsqrtf(q * (1.0f / D_) + 1e-5f);
    #pragma unroll
    for (int i = 0; i < 4; i++) {
        int c = tid + 256 * i;
        g_hn_h[row * D_ + c] = __float2half((v[i] - m) * rstd * g[c] + b[c]);
    }
}

// ---------------- host launch ----------------
extern "C" void kernel_launch(void* const* d_in, const int* in_sizes, int n_in,
                              void* d_out, int out_size) {
    const float* x   = (const float*)d_in[0];
    const float* Wr  = (const float*)d_in[1];
    const float* Wq  = (const float*)d_in[2];
    const float* Wk  = (const float*)d_in[3];
    const float* Wv  = (const float*)d_in[4];
    const float* Wo  = (const float*)d_in[5];
    const float* W1  = (const float*)d_in[6];
    const float* b1  = (const float*)d_in[7];
    const float* W2  = (const float*)d_in[8];
    const float* b2  = (const float*)d_in[9];
    const float* g1  = (const float*)d_in[10];
    const float* be1 = (const float*)d_in[11];
    const float* g2  = (const float*)d_in[12];
    const float* be2 = (const float*)d_in[13];
    float* out = (float*)d_out;

    float  *p_h;
    __half *p_xn_h, *p_att_h, *p_hn_h, *p_ff1_h, *p_projQKV;
    __half *p_Wqkv_h, *p_Wo_h, *p_W1_h, *p_W2_h;
    int *p_off, *p_tok;
    cudaGetSymbolAddress((void**)&p_xn_h,   g_xn_h);
    cudaGetSymbolAddress((void**)&p_projQKV,g_projQKV);
    cudaGetSymbolAddress((void**)&p_att_h,  g_att_h);
    cudaGetSymbolAddress((void**)&p_h,      g_h);
    cudaGetSymbolAddress((void**)&p_hn_h,   g_hn_h);
    cudaGetSymbolAddress((void**)&p_ff1_h,  g_ff1_h);
    cudaGetSymbolAddress((void**)&p_Wqkv_h, g_Wqkv_h);
    cudaGetSymbolAddress((void**)&p_Wo_h,   g_Wo_h);
    cudaGetSymbolAddress((void**)&p_W1_h,   g_W1_h);
    cudaGetSymbolAddress((void**)&p_W2_h,   g_W2_h);
    cudaGetSymbolAddress((void**)&p_off,    g_off);
    cudaGetSymbolAddress((void**)&p_tok,    g_tok);

    const long long EDD  = (long long)E_ * D_ * D_;
    const long long FFDD = (long long)FF_ * D_ * D_;
    const long long DD   = (long long)D_ * D_;
    cudaFuncSetAttribute(gemm_h,
                         cudaFuncAttributeMaxDynamicSharedMemorySize, GH_SMEM);
    cudaFuncSetAttribute(flash_attn_h,
                         cudaFuncAttributeMaxDynamicSharedMemorySize, FAH_SMEM);

    // single fused weight conversion
    {
        long long n8e = EDD / 8, n8f = FFDD / 8;
        long long c1 = n8e, c2 = 2*n8e, c3 = 3*n8e, c4 = 4*n8e,
                  c5 = 4*n8e + n8f, c6 = 4*n8e + 2*n8f;
        int blocks = (int)((c6 + 255) / 256);
        f2h_all_kernel<<<blocks, 256>>>(Wq, Wk, Wv, Wo, W1, W2,
            p_Wqkv_h, p_Wqkv_h + EDD, p_Wqkv_h + 2*EDD, p_Wo_h, p_W1_h, p_W2_h,
            c1, c2, c3, c4, c5, c6);
    }

    ln1_kernel<<<T_, 256>>>(x, g1, be1);
    router_kernel<<<T_ / 8, 256>>>(x, Wr, g1, be1);
    scan_scatter_lb_kernel<<<1, 1024>>>(out, out_size);

    // merged grouped QKV GEMM: z = p*E + e  (y=12: max expert load 1536 rows)
    gemm_h<<<dim3(D_ / 128, 12, 3 * E_), 256, GH_SMEM>>>(
        p_xn_h, p_Wqkv_h, nullptr, p_projQKV,
        D_, D_, D_, D_, E_, EDD, DD, (long long)A_ * D_,
        p_off, p_tok, A_, 0, nullptr, nullptr);
    combine_qkv_kernel<<<T_, 256>>>();

    flash_attn_h<<<dim3(N_ / 128, B_ * H_), 256, FAH_SMEM>>>();

    // grouped O projection (into proj slot 0); combine fused into LN2
    gemm_h<<<dim3(D_ / 128, 12, E_), 256, GH_SMEM>>>(
        p_att_h, p_Wo_h, nullptr, p_projQKV,
        D_, D_, D_, D_, E_, 0, DD, 0,
        p_off, p_tok, A_, 0, nullptr, nullptr);

    ln2_fused_kernel<<<T_, 256>>>(x, g2, be2);

    // FFN1
    gemm_h<<<dim3(FF_ * D_ / 128, T_ / 128, 1), 256, GH_SMEM>>>(
        p_hn_h, p_W1_h, nullptr, p_ff1_h,
        D_, D_, D_, FF_ * D_, 1, 0, 0, 0,
        nullptr, nullptr, T_, 2, b1, nullptr);

    // FFN2 -> d_out
    gemm_h<<<dim3(D_ / 128, T_ / 128, 1), 256, GH_SMEM>>>(
        p_ff1_h, p_W2_h, out, nullptr,
        FF_ * D_, FF_ * D_, FF_ * D_, D_, 1, 0, 0, 0,
        nullptr, nullptr, T_, 3, b2, p_h);
}